// round 3
// baseline (speedup 1.0000x reference)
#include <cuda_runtime.h>
#include <cuda_bf16.h>
#include <cstdint>

// ---------------------------------------------------------------------------
// ConditionalRealNVP log_prob, fused per-layer passes with warp-level bf16 MMA.
//
// Layout / plan:
//   - 4 kernel launches (one per coupling layer), x[B,4] fp32 + logdet[B] fp32
//     carried in __device__ scratch between passes.
//   - Persistent blocks: each block loads the layer's weights (s|t side by
//     side, bf16, padded strides for conflict-free ldmatrix) into smem ONCE,
//     then grid-strides over 128-sample tiles.
//   - Per tile, each of 8 warps owns 16 rows end-to-end:
//       GEMM1 [16x80]x[80x256] -> GELU -> (C->A repack in regs)
//       GEMM2 [16x128]x[128x128] per net -> GELU -> (C->A repack)
//       GEMM3 [16x128]x[128x8(pad)] per net -> s,t
//     then epilogue: x[trans] = x[trans]*exp(s)+t, logdet += s0+s1,
//     last layer computes log_pz + logdet.
// ---------------------------------------------------------------------------

#define BTOT   524288
#define MTILE  128
#define NTILES (BTOT / MTILE)   // 4096
#define XP_LD  88               // 66 used, pad->88 (conflict-free ldmatrix)
#define W_LD   264              // 256 used, pad->264 (conflict-free)
#define W3_LD  16

// smem byte offsets (all 128B aligned)
#define OFF_W1  0                         // 80*264*2  = 42240
#define OFF_W2  42240                     // 128*264*2 = 67584
#define OFF_W3  109824                    // 128*16*2  = 4096
#define OFF_XP  113920                    // 128*88*2  = 22528
#define OFF_XA  136448                    // 128*4*4   = 2048
#define OFF_B1  138496                    // 256*4     = 1024
#define OFF_B2  139520                    // 256*4     = 1024
#define OFF_B3  140544                    // 4*4       = 16
#define SMEM_BYTES 140560

__device__ float g_x[BTOT * 4];
__device__ float g_ld[BTOT];

__device__ __forceinline__ uint32_t smem_u32(const void* p) {
    return static_cast<uint32_t>(__cvta_generic_to_shared(p));
}
__device__ __forceinline__ void ldsm_x4(uint32_t a, uint32_t& r0, uint32_t& r1,
                                        uint32_t& r2, uint32_t& r3) {
    asm volatile("ldmatrix.sync.aligned.m8n8.x4.shared.b16 {%0,%1,%2,%3},[%4];"
                 : "=r"(r0), "=r"(r1), "=r"(r2), "=r"(r3) : "r"(a));
}
__device__ __forceinline__ void ldsm_x4t(uint32_t a, uint32_t& r0, uint32_t& r1,
                                         uint32_t& r2, uint32_t& r3) {
    asm volatile("ldmatrix.sync.aligned.m8n8.x4.trans.shared.b16 {%0,%1,%2,%3},[%4];"
                 : "=r"(r0), "=r"(r1), "=r"(r2), "=r"(r3) : "r"(a));
}
__device__ __forceinline__ void ldsm_x2t(uint32_t a, uint32_t& r0, uint32_t& r1) {
    asm volatile("ldmatrix.sync.aligned.m8n8.x2.trans.shared.b16 {%0,%1},[%2];"
                 : "=r"(r0), "=r"(r1) : "r"(a));
}
__device__ __forceinline__ void mma_bf16(float* c, const uint32_t* a,
                                         uint32_t b0, uint32_t b1) {
    asm volatile(
        "mma.sync.aligned.m16n8k16.row.col.f32.bf16.bf16.f32 "
        "{%0,%1,%2,%3},{%4,%5,%6,%7},{%8,%9},{%0,%1,%2,%3};"
        : "+f"(c[0]), "+f"(c[1]), "+f"(c[2]), "+f"(c[3])
        : "r"(a[0]), "r"(a[1]), "r"(a[2]), "r"(a[3]), "r"(b0), "r"(b1));
}
__device__ __forceinline__ uint32_t pack_bf2(float lo, float hi) {
    __nv_bfloat162 v = __floats2bfloat162_rn(lo, hi);
    return *reinterpret_cast<uint32_t*>(&v);
}
// tanh-approx GELU in sigmoid form: x * sigmoid(1.595769*x*(1+0.044715*x^2))
__device__ __forceinline__ float gelu(float x) {
    float u = 1.5957691216057308f * x * (1.0f + 0.044715f * x * x);
    return x / (1.0f + __expf(-u));
}

template <int LYR>
__global__ void __launch_bounds__(256, 1)
nvp_layer(const float* __restrict__ theta, const float* __restrict__ h,
          const float* __restrict__ w1s, const float* __restrict__ b1s,
          const float* __restrict__ w2s, const float* __restrict__ b2s,
          const float* __restrict__ w3s, const float* __restrict__ b3s,
          const float* __restrict__ w1t, const float* __restrict__ b1t,
          const float* __restrict__ w2t, const float* __restrict__ b2t,
          const float* __restrict__ w3t, const float* __restrict__ b3t,
          float* __restrict__ out)
{
    constexpr bool FIRST = (LYR == 0);
    constexpr bool LAST  = (LYR == 3);
    // KEEP = ((0,1),(1,2),(2,3),(0,3)); TRANS = ((2,3),(0,3),(0,1),(1,2))
    constexpr int K0 = (LYR == 0) ? 0 : (LYR == 1) ? 1 : (LYR == 2) ? 2 : 0;
    constexpr int K1 = (LYR == 0) ? 1 : (LYR == 1) ? 2 : (LYR == 2) ? 3 : 3;
    constexpr int T0 = (LYR == 0) ? 2 : (LYR == 1) ? 0 : (LYR == 2) ? 0 : 1;
    constexpr int T1 = (LYR == 0) ? 3 : (LYR == 1) ? 3 : (LYR == 2) ? 1 : 2;

    extern __shared__ char smem[];
    __nv_bfloat16* sW1 = reinterpret_cast<__nv_bfloat16*>(smem + OFF_W1);
    __nv_bfloat16* sW2 = reinterpret_cast<__nv_bfloat16*>(smem + OFF_W2);
    __nv_bfloat16* sW3 = reinterpret_cast<__nv_bfloat16*>(smem + OFF_W3);
    __nv_bfloat16* sXP = reinterpret_cast<__nv_bfloat16*>(smem + OFF_XP);
    float* sXA = reinterpret_cast<float*>(smem + OFF_XA);
    float* sB1 = reinterpret_cast<float*>(smem + OFF_B1);
    float* sB2 = reinterpret_cast<float*>(smem + OFF_B2);
    float* sB3 = reinterpret_cast<float*>(smem + OFF_B3);

    const int tid = threadIdx.x;

    // ---- one-time per block: weights -> smem (bf16, s|t combined, padded) ----
    for (int idx = tid; idx < 80 * W_LD; idx += 256) {
        int k = idx / W_LD, c = idx - k * W_LD;
        float v = 0.0f;
        if (k < 66 && c < 256) v = (c < 128) ? w1s[k * 128 + c] : w1t[k * 128 + c - 128];
        sW1[idx] = __float2bfloat16(v);
    }
    for (int idx = tid; idx < 128 * W_LD; idx += 256) {
        int k = idx / W_LD, c = idx - k * W_LD;
        float v = 0.0f;
        if (c < 256) v = (c < 128) ? w2s[k * 128 + c] : w2t[k * 128 + c - 128];
        sW2[idx] = __float2bfloat16(v);
    }
    for (int idx = tid; idx < 128 * W3_LD; idx += 256) {
        int k = idx >> 4, c = idx & 15;
        float v = 0.0f;
        if (c < 2) v = w3s[k * 2 + c];
        else if (c >= 8 && c < 10) v = w3t[k * 2 + c - 8];
        sW3[idx] = __float2bfloat16(v);
    }
    for (int c = tid; c < 256; c += 256) {
        sB1[c] = (c < 128) ? b1s[c] : b1t[c - 128];
        sB2[c] = (c < 128) ? b2s[c] : b2t[c - 128];
    }
    if (tid < 4) sB3[tid] = (tid < 2) ? b3s[tid] : b3t[tid - 2];
    // zero xp pad cols [66,88) once (never rewritten)
    for (int idx = tid; idx < 128 * 22; idx += 256) {
        int r = idx / 22, c = 66 + (idx - r * 22);
        sXP[r * XP_LD + c] = __float2bfloat16(0.0f);
    }
    __syncthreads();

    const int warp = tid >> 5;
    const int lane = tid & 31;
    const int R0 = warp * 16;
    const int lg = lane >> 3;        // ldmatrix group 0..3
    const int lr = lane & 7;

    for (int tile = blockIdx.x; tile < NTILES; tile += gridDim.x) {
        __syncthreads();  // all warps done with previous tile's sXP/sXA
        const int base = tile * MTILE;

        // ---- build xp tile: cols[0..1]=x[keep], cols[2..65]=h, rest zero ----
        for (int idx = tid; idx < 128 * 16; idx += 256) {
            int r = idx >> 4, q = idx & 15;
            float4 hv = reinterpret_cast<const float4*>(h)[(base + r) * 16 + q];
            __nv_bfloat162* p =
                reinterpret_cast<__nv_bfloat162*>(&sXP[r * XP_LD + 2 + 4 * q]);
            p[0] = __floats2bfloat162_rn(hv.x, hv.y);
            p[1] = __floats2bfloat162_rn(hv.z, hv.w);
        }
        for (int r = tid; r < 128; r += 256) {
            float4 xv;
            if (FIRST) xv = reinterpret_cast<const float4*>(theta)[base + r];
            else       xv = reinterpret_cast<const float4*>(g_x)[base + r];
            reinterpret_cast<float4*>(sXA)[r] = xv;
            float xc[4] = {xv.x, xv.y, xv.z, xv.w};
            *reinterpret_cast<__nv_bfloat162*>(&sXP[r * XP_LD]) =
                __floats2bfloat162_rn(xc[K0], xc[K1]);
        }
        __syncthreads();

        // ---- GEMM1: A frags from xp (K=80) ----
        uint32_t axp[5][4];
        {
            int row = R0 + lr + (lg & 1) * 8;
            int colo = (lg >> 1) * 8;
            const __nv_bfloat16* pbase = &sXP[row * XP_LD + colo];
            #pragma unroll
            for (int ks = 0; ks < 5; ks++) {
                ldsm_x4(smem_u32(pbase + ks * 16),
                        axp[ks][0], axp[ks][1], axp[ks][2], axp[ks][3]);
            }
        }
        // hid1 kept as 16 A-fragments (cols: [0..127]=s-half, [128..255]=t-half)
        uint32_t hf[16][4];
        #pragma unroll
        for (int ch = 0; ch < 4; ch++) {
            float acc[8][4] = {};
            #pragma unroll
            for (int ks = 0; ks < 5; ks++) {
                int krow = ks * 16 + lr + (lg & 1) * 8;
                int cb = ch * 64 + (lg >> 1) * 8;
                uint32_t bf[4][4];
                #pragma unroll
                for (int p = 0; p < 4; p++)
                    ldsm_x4t(smem_u32(&sW1[krow * W_LD + cb + p * 16]),
                             bf[p][0], bf[p][1], bf[p][2], bf[p][3]);
                #pragma unroll
                for (int p = 0; p < 4; p++) {
                    mma_bf16(acc[2 * p],     axp[ks], bf[p][0], bf[p][1]);
                    mma_bf16(acc[2 * p + 1], axp[ks], bf[p][2], bf[p][3]);
                }
            }
            #pragma unroll
            for (int j = 0; j < 8; j++) {
                int c = ch * 64 + j * 8 + (lane & 3) * 2;
                float2 bb = *reinterpret_cast<const float2*>(&sB1[c]);
                acc[j][0] = gelu(acc[j][0] + bb.x);
                acc[j][1] = gelu(acc[j][1] + bb.y);
                acc[j][2] = gelu(acc[j][2] + bb.x);
                acc[j][3] = gelu(acc[j][3] + bb.y);
            }
            #pragma unroll
            for (int kf = 0; kf < 4; kf++) {
                hf[ch * 4 + kf][0] = pack_bf2(acc[2 * kf][0], acc[2 * kf][1]);
                hf[ch * 4 + kf][1] = pack_bf2(acc[2 * kf][2], acc[2 * kf][3]);
                hf[ch * 4 + kf][2] = pack_bf2(acc[2 * kf + 1][0], acc[2 * kf + 1][1]);
                hf[ch * 4 + kf][3] = pack_bf2(acc[2 * kf + 1][2], acc[2 * kf + 1][3]);
            }
        }

        // ---- GEMM2 (+fused GEMM3) per net ----
        float outs[2][4];
        #pragma unroll
        for (int net = 0; net < 2; net++) {
            float acc3[4] = {0.f, 0.f, 0.f, 0.f};
            #pragma unroll
            for (int cc = 0; cc < 2; cc++) {
                float acc[8][4] = {};
                #pragma unroll
                for (int ks = 0; ks < 8; ks++) {
                    int krow = ks * 16 + lr + (lg & 1) * 8;
                    int cb = net * 128 + cc * 64 + (lg >> 1) * 8;
                    uint32_t bf[4][4];
                    #pragma unroll
                    for (int p = 0; p < 4; p++)
                        ldsm_x4t(smem_u32(&sW2[krow * W_LD + cb + p * 16]),
                                 bf[p][0], bf[p][1], bf[p][2], bf[p][3]);
                    const uint32_t* A = hf[net * 8 + ks];
                    #pragma unroll
                    for (int p = 0; p < 4; p++) {
                        mma_bf16(acc[2 * p],     A, bf[p][0], bf[p][1]);
                        mma_bf16(acc[2 * p + 1], A, bf[p][2], bf[p][3]);
                    }
                }
                uint32_t af[4][4];
                #pragma unroll
                for (int j = 0; j < 8; j++) {
                    int c = net * 128 + cc * 64 + j * 8 + (lane & 3) * 2;
                    float2 bb = *reinterpret_cast<const float2*>(&sB2[c]);
                    acc[j][0] = gelu(acc[j][0] + bb.x);
                    acc[j][1] = gelu(acc[j][1] + bb.y);
                    acc[j][2] = gelu(acc[j][2] + bb.x);
                    acc[j][3] = gelu(acc[j][3] + bb.y);
                }
                #pragma unroll
                for (int kf = 0; kf < 4; kf++) {
                    af[kf][0] = pack_bf2(acc[2 * kf][0], acc[2 * kf][1]);
                    af[kf][1] = pack_bf2(acc[2 * kf][2], acc[2 * kf][3]);
                    af[kf][2] = pack_bf2(acc[2 * kf + 1][0], acc[2 * kf + 1][1]);
                    af[kf][3] = pack_bf2(acc[2 * kf + 1][2], acc[2 * kf + 1][3]);
                }
                // GEMM3 partial: hid2 chunk (K=64) x W3[net] (N=8, cols 0..1 valid)
                #pragma unroll
                for (int kf = 0; kf < 4; kf++) {
                    int k0 = cc * 64 + kf * 16;
                    uint32_t addr =
                        smem_u32(&sW3[(k0 + (lane & 15)) * W3_LD + net * 8]);
                    uint32_t b0, b1;
                    ldsm_x2t(addr, b0, b1);
                    mma_bf16(acc3, af[kf], b0, b1);
                }
            }
            #pragma unroll
            for (int i = 0; i < 4; i++) outs[net][i] = acc3[i];
        }

        // ---- epilogue: lanes with (lane&3)==0 hold cols 0,1 of s/t frags ----
        if ((lane & 3) == 0) {
            int r1 = lane >> 2;
            float b3s0 = sB3[0], b3s1 = sB3[1], b3t0 = sB3[2], b3t1 = sB3[3];
            #pragma unroll
            for (int half = 0; half < 2; half++) {
                int row = R0 + r1 + half * 8;
                int b = base + row;
                float s0 = outs[0][half * 2 + 0] + b3s0;
                float s1 = outs[0][half * 2 + 1] + b3s1;
                float t0 = outs[1][half * 2 + 0] + b3t0;
                float t1 = outs[1][half * 2 + 1] + b3t1;
                float4 xv = reinterpret_cast<const float4*>(sXA)[row];
                float xc[4] = {xv.x, xv.y, xv.z, xv.w};
                float nx0 = xc[T0] * __expf(s0) + t0;
                float nx1 = xc[T1] * __expf(s1) + t1;
                float ld = s0 + s1;
                if (!FIRST) ld += g_ld[b];
                xc[T0] = nx0;
                xc[T1] = nx1;
                if (!LAST) {
                    reinterpret_cast<float4*>(g_x)[b] =
                        make_float4(xc[0], xc[1], xc[2], xc[3]);
                    g_ld[b] = ld;
                } else {
                    float ss = xc[0] * xc[0] + xc[1] * xc[1] +
                               xc[2] * xc[2] + xc[3] * xc[3];
                    out[b] = -0.5f * ss - 3.6757541328186907f + ld;
                }
            }
        }
    }
}

extern "C" void kernel_launch(void* const* d_in, const int* in_sizes, int n_in,
                              void* d_out, int out_size)
{
    const float* theta = (const float*)d_in[0];
    const float* h     = (const float*)d_in[1];
    const float* sW1   = (const float*)d_in[2];
    const float* sb1   = (const float*)d_in[3];
    const float* sW2   = (const float*)d_in[4];
    const float* sb2   = (const float*)d_in[5];
    const float* sW3   = (const float*)d_in[6];
    const float* sb3   = (const float*)d_in[7];
    const float* tW1   = (const float*)d_in[8];
    const float* tb1   = (const float*)d_in[9];
    const float* tW2   = (const float*)d_in[10];
    const float* tb2   = (const float*)d_in[11];
    const float* tW3   = (const float*)d_in[12];
    const float* tb3   = (const float*)d_in[13];
    float* out = (float*)d_out;

    int nsm = 148;
    cudaDeviceGetAttribute(&nsm, cudaDevAttrMultiProcessorCount, 0);

    cudaFuncSetAttribute(nvp_layer<0>, cudaFuncAttributeMaxDynamicSharedMemorySize, SMEM_BYTES);
    cudaFuncSetAttribute(nvp_layer<1>, cudaFuncAttributeMaxDynamicSharedMemorySize, SMEM_BYTES);
    cudaFuncSetAttribute(nvp_layer<2>, cudaFuncAttributeMaxDynamicSharedMemorySize, SMEM_BYTES);
    cudaFuncSetAttribute(nvp_layer<3>, cudaFuncAttributeMaxDynamicSharedMemorySize, SMEM_BYTES);

    dim3 grid(nsm), blk(256);
    #define ARGS(L) theta, h,                                        \
        sW1 + (L) * 66 * 128, sb1 + (L) * 128,                       \
        sW2 + (L) * 128 * 128, sb2 + (L) * 128,                      \
        sW3 + (L) * 128 * 2, sb3 + (L) * 2,                          \
        tW1 + (L) * 66 * 128, tb1 + (L) * 128,                       \
        tW2 + (L) * 128 * 128, tb2 + (L) * 128,                      \
        tW3 + (L) * 128 * 2, tb3 + (L) * 2, out

    nvp_layer<0><<<grid, blk, SMEM_BYTES>>>(ARGS(0));
    nvp_layer<1><<<grid, blk, SMEM_BYTES>>>(ARGS(1));
    nvp_layer<2><<<grid, blk, SMEM_BYTES>>>(ARGS(2));
    nvp_layer<3><<<grid, blk, SMEM_BYTES>>>(ARGS(3));
    #undef ARGS
}

// round 4
// speedup vs baseline: 1.4726x; 1.4726x over previous
#include <cuda_runtime.h>
#include <cuda_bf16.h>
#include <cstdint>

// ---------------------------------------------------------------------------
// ConditionalRealNVP log_prob, fused per-layer passes with warp-level bf16 MMA.
//
// R3 change vs R2: net-split warp specialization. 512 threads / 16 warps per
// CTA; warps 0-7 compute the s-net end-to-end for their 16 rows, warps 8-15
// compute the t-net for the same rows. Halves per-warp register state
// (169 -> ~115 regs) so the full 512-thread CTA is resident: occupancy
// 12.5% -> 25%, doubling latency hiding on the ldmatrix->mma chains.
// ---------------------------------------------------------------------------

#define BTOT   524288
#define MTILE  128
#define NTILES (BTOT / MTILE)   // 4096
#define XP_LD  88               // 66 used, pad->88 (conflict-free ldmatrix)
#define W_LD   264              // 256 used, pad->264 (conflict-free)
#define W3_LD  16

// smem byte offsets (all 16B aligned)
#define OFF_W1  0                         // 80*264*2  = 42240
#define OFF_W2  42240                     // 128*264*2 = 67584
#define OFF_W3  109824                    // 128*16*2  = 4096
#define OFF_XP  113920                    // 128*88*2  = 22528
#define OFF_XA  136448                    // 128*4*4   = 2048
#define OFF_B1  138496                    // 256*4     = 1024
#define OFF_B2  139520                    // 256*4     = 1024
#define OFF_B3  140544                    // 4*4       = 16
#define OFF_ST  140560                    // 2*128*2*4 = 2048 (s/t staging)
#define SMEM_BYTES 142608

#define NTHREADS 512

__device__ float g_x[BTOT * 4];
__device__ float g_ld[BTOT];

__device__ __forceinline__ uint32_t smem_u32(const void* p) {
    return static_cast<uint32_t>(__cvta_generic_to_shared(p));
}
__device__ __forceinline__ void ldsm_x4(uint32_t a, uint32_t& r0, uint32_t& r1,
                                        uint32_t& r2, uint32_t& r3) {
    asm volatile("ldmatrix.sync.aligned.m8n8.x4.shared.b16 {%0,%1,%2,%3},[%4];"
                 : "=r"(r0), "=r"(r1), "=r"(r2), "=r"(r3) : "r"(a));
}
__device__ __forceinline__ void ldsm_x4t(uint32_t a, uint32_t& r0, uint32_t& r1,
                                         uint32_t& r2, uint32_t& r3) {
    asm volatile("ldmatrix.sync.aligned.m8n8.x4.trans.shared.b16 {%0,%1,%2,%3},[%4];"
                 : "=r"(r0), "=r"(r1), "=r"(r2), "=r"(r3) : "r"(a));
}
__device__ __forceinline__ void ldsm_x2t(uint32_t a, uint32_t& r0, uint32_t& r1) {
    asm volatile("ldmatrix.sync.aligned.m8n8.x2.trans.shared.b16 {%0,%1},[%2];"
                 : "=r"(r0), "=r"(r1) : "r"(a));
}
__device__ __forceinline__ void mma_bf16(float* c, const uint32_t* a,
                                         uint32_t b0, uint32_t b1) {
    asm volatile(
        "mma.sync.aligned.m16n8k16.row.col.f32.bf16.bf16.f32 "
        "{%0,%1,%2,%3},{%4,%5,%6,%7},{%8,%9},{%0,%1,%2,%3};"
        : "+f"(c[0]), "+f"(c[1]), "+f"(c[2]), "+f"(c[3])
        : "r"(a[0]), "r"(a[1]), "r"(a[2]), "r"(a[3]), "r"(b0), "r"(b1));
}
__device__ __forceinline__ uint32_t pack_bf2(float lo, float hi) {
    __nv_bfloat162 v = __floats2bfloat162_rn(lo, hi);
    return *reinterpret_cast<uint32_t*>(&v);
}
// tanh-approx GELU in sigmoid form: x * sigmoid(1.595769*x*(1+0.044715*x^2))
__device__ __forceinline__ float gelu(float x) {
    float u = 1.5957691216057308f * x * (1.0f + 0.044715f * x * x);
    return x / (1.0f + __expf(-u));
}

template <int LYR>
__global__ void __launch_bounds__(NTHREADS, 1)
nvp_layer(const float* __restrict__ theta, const float* __restrict__ h,
          const float* __restrict__ w1s, const float* __restrict__ b1s,
          const float* __restrict__ w2s, const float* __restrict__ b2s,
          const float* __restrict__ w3s, const float* __restrict__ b3s,
          const float* __restrict__ w1t, const float* __restrict__ b1t,
          const float* __restrict__ w2t, const float* __restrict__ b2t,
          const float* __restrict__ w3t, const float* __restrict__ b3t,
          float* __restrict__ out)
{
    constexpr bool FIRST = (LYR == 0);
    constexpr bool LAST  = (LYR == 3);
    // KEEP = ((0,1),(1,2),(2,3),(0,3)); TRANS = ((2,3),(0,3),(0,1),(1,2))
    constexpr int K0 = (LYR == 0) ? 0 : (LYR == 1) ? 1 : (LYR == 2) ? 2 : 0;
    constexpr int K1 = (LYR == 0) ? 1 : (LYR == 1) ? 2 : (LYR == 2) ? 3 : 3;
    constexpr int T0 = (LYR == 0) ? 2 : (LYR == 1) ? 0 : (LYR == 2) ? 0 : 1;
    constexpr int T1 = (LYR == 0) ? 3 : (LYR == 1) ? 3 : (LYR == 2) ? 1 : 2;

    extern __shared__ char smem[];
    __nv_bfloat16* sW1 = reinterpret_cast<__nv_bfloat16*>(smem + OFF_W1);
    __nv_bfloat16* sW2 = reinterpret_cast<__nv_bfloat16*>(smem + OFF_W2);
    __nv_bfloat16* sW3 = reinterpret_cast<__nv_bfloat16*>(smem + OFF_W3);
    __nv_bfloat16* sXP = reinterpret_cast<__nv_bfloat16*>(smem + OFF_XP);
    float* sXA = reinterpret_cast<float*>(smem + OFF_XA);
    float* sB1 = reinterpret_cast<float*>(smem + OFF_B1);
    float* sB2 = reinterpret_cast<float*>(smem + OFF_B2);
    float* sB3 = reinterpret_cast<float*>(smem + OFF_B3);
    float* sST = reinterpret_cast<float*>(smem + OFF_ST);  // [2][128][2]

    const int tid = threadIdx.x;

    // ---- one-time per block: weights -> smem (bf16, s|t combined, padded) ----
    for (int idx = tid; idx < 80 * W_LD; idx += NTHREADS) {
        int k = idx / W_LD, c = idx - k * W_LD;
        float v = 0.0f;
        if (k < 66 && c < 256) v = (c < 128) ? w1s[k * 128 + c] : w1t[k * 128 + c - 128];
        sW1[idx] = __float2bfloat16(v);
    }
    for (int idx = tid; idx < 128 * W_LD; idx += NTHREADS) {
        int k = idx / W_LD, c = idx - k * W_LD;
        float v = 0.0f;
        if (c < 256) v = (c < 128) ? w2s[k * 128 + c] : w2t[k * 128 + c - 128];
        sW2[idx] = __float2bfloat16(v);
    }
    for (int idx = tid; idx < 128 * W3_LD; idx += NTHREADS) {
        int k = idx >> 4, c = idx & 15;
        float v = 0.0f;
        if (c < 2) v = w3s[k * 2 + c];
        else if (c >= 8 && c < 10) v = w3t[k * 2 + c - 8];
        sW3[idx] = __float2bfloat16(v);
    }
    for (int c = tid; c < 256; c += NTHREADS) {
        sB1[c] = (c < 128) ? b1s[c] : b1t[c - 128];
        sB2[c] = (c < 128) ? b2s[c] : b2t[c - 128];
    }
    if (tid < 4) sB3[tid] = (tid < 2) ? b3s[tid] : b3t[tid - 2];
    // zero xp pad cols [66,88) once (never rewritten)
    for (int idx = tid; idx < 128 * 22; idx += NTHREADS) {
        int r = idx / 22, c = 66 + (idx - r * 22);
        sXP[r * XP_LD + c] = __float2bfloat16(0.0f);
    }
    __syncthreads();

    const int warp = tid >> 5;
    const int lane = tid & 31;
    const int net  = warp >> 3;       // 0 = s-net (warps 0-7), 1 = t-net (8-15)
    const int R0   = (warp & 7) * 16; // row block shared by warp pair
    const int lg   = lane >> 3;       // ldmatrix group 0..3
    const int lr   = lane & 7;

    for (int tile = blockIdx.x; tile < NTILES; tile += gridDim.x) {
        __syncthreads();  // previous tile's epilogue reads of sXA/sST done
        const int base = tile * MTILE;

        // ---- build xp tile: cols[0..1]=x[keep], cols[2..65]=h, rest zero ----
        for (int idx = tid; idx < 128 * 16; idx += NTHREADS) {
            int r = idx >> 4, q = idx & 15;
            float4 hv = reinterpret_cast<const float4*>(h)[(base + r) * 16 + q];
            __nv_bfloat162* p =
                reinterpret_cast<__nv_bfloat162*>(&sXP[r * XP_LD + 2 + 4 * q]);
            p[0] = __floats2bfloat162_rn(hv.x, hv.y);
            p[1] = __floats2bfloat162_rn(hv.z, hv.w);
        }
        if (tid < 128) {
            int r = tid;
            float4 xv;
            if (FIRST) xv = reinterpret_cast<const float4*>(theta)[base + r];
            else       xv = reinterpret_cast<const float4*>(g_x)[base + r];
            reinterpret_cast<float4*>(sXA)[r] = xv;
            float xc[4] = {xv.x, xv.y, xv.z, xv.w};
            *reinterpret_cast<__nv_bfloat162*>(&sXP[r * XP_LD]) =
                __floats2bfloat162_rn(xc[K0], xc[K1]);
        }
        __syncthreads();

        // ---- GEMM1: A frags from xp (K=80), this warp's net only (128 cols) ----
        uint32_t axp[5][4];
        {
            int row = R0 + lr + (lg & 1) * 8;
            int colo = (lg >> 1) * 8;
            const __nv_bfloat16* pbase = &sXP[row * XP_LD + colo];
            #pragma unroll
            for (int ks = 0; ks < 5; ks++) {
                ldsm_x4(smem_u32(pbase + ks * 16),
                        axp[ks][0], axp[ks][1], axp[ks][2], axp[ks][3]);
            }
        }
        // hid1 kept as 8 A-fragments (K-local 0..127 of this net's half)
        uint32_t hf[8][4];
        #pragma unroll
        for (int ch = 0; ch < 2; ch++) {
            float acc[8][4] = {};
            #pragma unroll
            for (int ks = 0; ks < 5; ks++) {
                int krow = ks * 16 + lr + (lg & 1) * 8;
                int cb = net * 128 + ch * 64 + (lg >> 1) * 8;
                uint32_t bf[4][4];
                #pragma unroll
                for (int p = 0; p < 4; p++)
                    ldsm_x4t(smem_u32(&sW1[krow * W_LD + cb + p * 16]),
                             bf[p][0], bf[p][1], bf[p][2], bf[p][3]);
                #pragma unroll
                for (int p = 0; p < 4; p++) {
                    mma_bf16(acc[2 * p],     axp[ks], bf[p][0], bf[p][1]);
                    mma_bf16(acc[2 * p + 1], axp[ks], bf[p][2], bf[p][3]);
                }
            }
            #pragma unroll
            for (int j = 0; j < 8; j++) {
                int c = net * 128 + ch * 64 + j * 8 + (lane & 3) * 2;
                float2 bb = *reinterpret_cast<const float2*>(&sB1[c]);
                acc[j][0] = gelu(acc[j][0] + bb.x);
                acc[j][1] = gelu(acc[j][1] + bb.y);
                acc[j][2] = gelu(acc[j][2] + bb.x);
                acc[j][3] = gelu(acc[j][3] + bb.y);
            }
            #pragma unroll
            for (int kf = 0; kf < 4; kf++) {
                hf[ch * 4 + kf][0] = pack_bf2(acc[2 * kf][0], acc[2 * kf][1]);
                hf[ch * 4 + kf][1] = pack_bf2(acc[2 * kf][2], acc[2 * kf][3]);
                hf[ch * 4 + kf][2] = pack_bf2(acc[2 * kf + 1][0], acc[2 * kf + 1][1]);
                hf[ch * 4 + kf][3] = pack_bf2(acc[2 * kf + 1][2], acc[2 * kf + 1][3]);
            }
        }

        // ---- GEMM2 (+fused GEMM3), this warp's net ----
        float acc3[4] = {0.f, 0.f, 0.f, 0.f};
        #pragma unroll
        for (int cc = 0; cc < 2; cc++) {
            float acc[8][4] = {};
            #pragma unroll
            for (int ks = 0; ks < 8; ks++) {
                int krow = ks * 16 + lr + (lg & 1) * 8;
                int cb = net * 128 + cc * 64 + (lg >> 1) * 8;
                uint32_t bf[4][4];
                #pragma unroll
                for (int p = 0; p < 4; p++)
                    ldsm_x4t(smem_u32(&sW2[krow * W_LD + cb + p * 16]),
                             bf[p][0], bf[p][1], bf[p][2], bf[p][3]);
                const uint32_t* A = hf[ks];
                #pragma unroll
                for (int p = 0; p < 4; p++) {
                    mma_bf16(acc[2 * p],     A, bf[p][0], bf[p][1]);
                    mma_bf16(acc[2 * p + 1], A, bf[p][2], bf[p][3]);
                }
            }
            uint32_t af[4][4];
            #pragma unroll
            for (int j = 0; j < 8; j++) {
                int c = net * 128 + cc * 64 + j * 8 + (lane & 3) * 2;
                float2 bb = *reinterpret_cast<const float2*>(&sB2[c]);
                acc[j][0] = gelu(acc[j][0] + bb.x);
                acc[j][1] = gelu(acc[j][1] + bb.y);
                acc[j][2] = gelu(acc[j][2] + bb.x);
                acc[j][3] = gelu(acc[j][3] + bb.y);
            }
            #pragma unroll
            for (int kf = 0; kf < 4; kf++) {
                af[kf][0] = pack_bf2(acc[2 * kf][0], acc[2 * kf][1]);
                af[kf][1] = pack_bf2(acc[2 * kf][2], acc[2 * kf][3]);
                af[kf][2] = pack_bf2(acc[2 * kf + 1][0], acc[2 * kf + 1][1]);
                af[kf][3] = pack_bf2(acc[2 * kf + 1][2], acc[2 * kf + 1][3]);
            }
            // GEMM3 partial: hid2 chunk (K=64) x W3[net] (N=8, cols 0..1 valid)
            #pragma unroll
            for (int kf = 0; kf < 4; kf++) {
                int k0 = cc * 64 + kf * 16;
                uint32_t addr =
                    smem_u32(&sW3[(k0 + (lane & 15)) * W3_LD + net * 8]);
                uint32_t b0, b1;
                ldsm_x2t(addr, b0, b1);
                mma_bf16(acc3, af[kf], b0, b1);
            }
        }

        // ---- stage this net's (c0,c1) per row into smem ----
        if ((lane & 3) == 0) {
            int r1 = lane >> 2;
            #pragma unroll
            for (int half = 0; half < 2; half++) {
                int row = R0 + r1 + half * 8;
                sST[(net * 128 + row) * 2 + 0] = acc3[half * 2 + 0];
                sST[(net * 128 + row) * 2 + 1] = acc3[half * 2 + 1];
            }
        }
        __syncthreads();

        // ---- epilogue: one thread per row ----
        if (tid < 128) {
            int row = tid;
            int b = base + row;
            float s0 = sST[row * 2 + 0] + sB3[0];
            float s1 = sST[row * 2 + 1] + sB3[1];
            float t0 = sST[(128 + row) * 2 + 0] + sB3[2];
            float t1 = sST[(128 + row) * 2 + 1] + sB3[3];
            float4 xv = reinterpret_cast<const float4*>(sXA)[row];
            float xc[4] = {xv.x, xv.y, xv.z, xv.w};
            float nx0 = xc[T0] * __expf(s0) + t0;
            float nx1 = xc[T1] * __expf(s1) + t1;
            float ld = s0 + s1;
            if (!FIRST) ld += g_ld[b];
            xc[T0] = nx0;
            xc[T1] = nx1;
            if (!LAST) {
                reinterpret_cast<float4*>(g_x)[b] =
                    make_float4(xc[0], xc[1], xc[2], xc[3]);
                g_ld[b] = ld;
            } else {
                float ss = xc[0] * xc[0] + xc[1] * xc[1] +
                           xc[2] * xc[2] + xc[3] * xc[3];
                out[b] = -0.5f * ss - 3.6757541328186907f + ld;
            }
        }
    }
}

extern "C" void kernel_launch(void* const* d_in, const int* in_sizes, int n_in,
                              void* d_out, int out_size)
{
    const float* theta = (const float*)d_in[0];
    const float* h     = (const float*)d_in[1];
    const float* sW1   = (const float*)d_in[2];
    const float* sb1   = (const float*)d_in[3];
    const float* sW2   = (const float*)d_in[4];
    const float* sb2   = (const float*)d_in[5];
    const float* sW3   = (const float*)d_in[6];
    const float* sb3   = (const float*)d_in[7];
    const float* tW1   = (const float*)d_in[8];
    const float* tb1   = (const float*)d_in[9];
    const float* tW2   = (const float*)d_in[10];
    const float* tb2   = (const float*)d_in[11];
    const float* tW3   = (const float*)d_in[12];
    const float* tb3   = (const float*)d_in[13];
    float* out = (float*)d_out;

    int nsm = 148;
    cudaDeviceGetAttribute(&nsm, cudaDevAttrMultiProcessorCount, 0);

    cudaFuncSetAttribute(nvp_layer<0>, cudaFuncAttributeMaxDynamicSharedMemorySize, SMEM_BYTES);
    cudaFuncSetAttribute(nvp_layer<1>, cudaFuncAttributeMaxDynamicSharedMemorySize, SMEM_BYTES);
    cudaFuncSetAttribute(nvp_layer<2>, cudaFuncAttributeMaxDynamicSharedMemorySize, SMEM_BYTES);
    cudaFuncSetAttribute(nvp_layer<3>, cudaFuncAttributeMaxDynamicSharedMemorySize, SMEM_BYTES);

    dim3 grid(nsm), blk(NTHREADS);
    #define ARGS(L) theta, h,                                        \
        sW1 + (L) * 66 * 128, sb1 + (L) * 128,                       \
        sW2 + (L) * 128 * 128, sb2 + (L) * 128,                      \
        sW3 + (L) * 128 * 2, sb3 + (L) * 2,                          \
        tW1 + (L) * 66 * 128, tb1 + (L) * 128,                       \
        tW2 + (L) * 128 * 128, tb2 + (L) * 128,                      \
        tW3 + (L) * 128 * 2, tb3 + (L) * 2, out

    nvp_layer<0><<<grid, blk, SMEM_BYTES>>>(ARGS(0));
    nvp_layer<1><<<grid, blk, SMEM_BYTES>>>(ARGS(1));
    nvp_layer<2><<<grid, blk, SMEM_BYTES>>>(ARGS(2));
    nvp_layer<3><<<grid, blk, SMEM_BYTES>>>(ARGS(3));
    #undef ARGS
}

// round 5
// speedup vs baseline: 2.5038x; 1.7003x over previous
#include <cuda_runtime.h>
#include <cuda_bf16.h>
#include <cstdint>

// ---------------------------------------------------------------------------
// ConditionalRealNVP log_prob, fused per-layer passes with warp-level bf16 MMA.
//
// R4 change vs R3: GELU via MUFU.TANH. Same tanh-approx function as before
// (x*sigmoid(1.5958u) == 0.5x(1+tanh(0.79788u))) but evaluated with the
// hardware tanh.approx.f32 instead of __expf + fp32 division: 10-12 instrs
// with a long serial chain -> 4 FMA ops + 1 MUFU. GELU was ~60% of issued
// instructions (fma pipe 21.6% >= tensor 20%, issue 39.7%).
// ---------------------------------------------------------------------------

#define BTOT   524288
#define MTILE  128
#define NTILES (BTOT / MTILE)   // 4096
#define XP_LD  88               // 66 used, pad->88 (conflict-free ldmatrix)
#define W_LD   264              // 256 used, pad->264 (conflict-free)
#define W3_LD  16

// smem byte offsets (all 16B aligned)
#define OFF_W1  0                         // 80*264*2  = 42240
#define OFF_W2  42240                     // 128*264*2 = 67584
#define OFF_W3  109824                    // 128*16*2  = 4096
#define OFF_XP  113920                    // 128*88*2  = 22528
#define OFF_XA  136448                    // 128*4*4   = 2048
#define OFF_B1  138496                    // 256*4     = 1024
#define OFF_B2  139520                    // 256*4     = 1024
#define OFF_B3  140544                    // 4*4       = 16
#define OFF_ST  140560                    // 2*128*2*4 = 2048 (s/t staging)
#define SMEM_BYTES 142608

#define NTHREADS 512

__device__ float g_x[BTOT * 4];
__device__ float g_ld[BTOT];

__device__ __forceinline__ uint32_t smem_u32(const void* p) {
    return static_cast<uint32_t>(__cvta_generic_to_shared(p));
}
__device__ __forceinline__ void ldsm_x4(uint32_t a, uint32_t& r0, uint32_t& r1,
                                        uint32_t& r2, uint32_t& r3) {
    asm volatile("ldmatrix.sync.aligned.m8n8.x4.shared.b16 {%0,%1,%2,%3},[%4];"
                 : "=r"(r0), "=r"(r1), "=r"(r2), "=r"(r3) : "r"(a));
}
__device__ __forceinline__ void ldsm_x4t(uint32_t a, uint32_t& r0, uint32_t& r1,
                                         uint32_t& r2, uint32_t& r3) {
    asm volatile("ldmatrix.sync.aligned.m8n8.x4.trans.shared.b16 {%0,%1,%2,%3},[%4];"
                 : "=r"(r0), "=r"(r1), "=r"(r2), "=r"(r3) : "r"(a));
}
__device__ __forceinline__ void ldsm_x2t(uint32_t a, uint32_t& r0, uint32_t& r1) {
    asm volatile("ldmatrix.sync.aligned.m8n8.x2.trans.shared.b16 {%0,%1},[%2];"
                 : "=r"(r0), "=r"(r1) : "r"(a));
}
__device__ __forceinline__ void mma_bf16(float* c, const uint32_t* a,
                                         uint32_t b0, uint32_t b1) {
    asm volatile(
        "mma.sync.aligned.m16n8k16.row.col.f32.bf16.bf16.f32 "
        "{%0,%1,%2,%3},{%4,%5,%6,%7},{%8,%9},{%0,%1,%2,%3};"
        : "+f"(c[0]), "+f"(c[1]), "+f"(c[2]), "+f"(c[3])
        : "r"(a[0]), "r"(a[1]), "r"(a[2]), "r"(a[3]), "r"(b0), "r"(b1));
}
__device__ __forceinline__ uint32_t pack_bf2(float lo, float hi) {
    __nv_bfloat162 v = __floats2bfloat162_rn(lo, hi);
    return *reinterpret_cast<uint32_t*>(&v);
}
// tanh-approx GELU: 0.5*x*(1 + tanh(0.79788456*(x + 0.044715*x^3)))
// == x * sigmoid(1.5957691*(x + 0.044715*x^3))  (same function as R3, but
// evaluated with MUFU.TANH: 4 fma-pipe ops + 1 MUFU, no division).
__device__ __forceinline__ float gelu(float x) {
    float x2 = x * x;
    float w  = fmaf(0.035677408136f, x2, 0.7978845608028654f);
    float u  = x * w;
    float th;
    asm("tanh.approx.f32 %0, %1;" : "=f"(th) : "f"(u));
    float hx = 0.5f * x;
    return fmaf(hx, th, hx);
}

template <int LYR>
__global__ void __launch_bounds__(NTHREADS, 1)
nvp_layer(const float* __restrict__ theta, const float* __restrict__ h,
          const float* __restrict__ w1s, const float* __restrict__ b1s,
          const float* __restrict__ w2s, const float* __restrict__ b2s,
          const float* __restrict__ w3s, const float* __restrict__ b3s,
          const float* __restrict__ w1t, const float* __restrict__ b1t,
          const float* __restrict__ w2t, const float* __restrict__ b2t,
          const float* __restrict__ w3t, const float* __restrict__ b3t,
          float* __restrict__ out)
{
    constexpr bool FIRST = (LYR == 0);
    constexpr bool LAST  = (LYR == 3);
    // KEEP = ((0,1),(1,2),(2,3),(0,3)); TRANS = ((2,3),(0,3),(0,1),(1,2))
    constexpr int K0 = (LYR == 0) ? 0 : (LYR == 1) ? 1 : (LYR == 2) ? 2 : 0;
    constexpr int K1 = (LYR == 0) ? 1 : (LYR == 1) ? 2 : (LYR == 2) ? 3 : 3;
    constexpr int T0 = (LYR == 0) ? 2 : (LYR == 1) ? 0 : (LYR == 2) ? 0 : 1;
    constexpr int T1 = (LYR == 0) ? 3 : (LYR == 1) ? 3 : (LYR == 2) ? 1 : 2;

    extern __shared__ char smem[];
    __nv_bfloat16* sW1 = reinterpret_cast<__nv_bfloat16*>(smem + OFF_W1);
    __nv_bfloat16* sW2 = reinterpret_cast<__nv_bfloat16*>(smem + OFF_W2);
    __nv_bfloat16* sW3 = reinterpret_cast<__nv_bfloat16*>(smem + OFF_W3);
    __nv_bfloat16* sXP = reinterpret_cast<__nv_bfloat16*>(smem + OFF_XP);
    float* sXA = reinterpret_cast<float*>(smem + OFF_XA);
    float* sB1 = reinterpret_cast<float*>(smem + OFF_B1);
    float* sB2 = reinterpret_cast<float*>(smem + OFF_B2);
    float* sB3 = reinterpret_cast<float*>(smem + OFF_B3);
    float* sST = reinterpret_cast<float*>(smem + OFF_ST);  // [2][128][2]

    const int tid = threadIdx.x;

    // ---- one-time per block: weights -> smem (bf16, s|t combined, padded) ----
    for (int idx = tid; idx < 80 * W_LD; idx += NTHREADS) {
        int k = idx / W_LD, c = idx - k * W_LD;
        float v = 0.0f;
        if (k < 66 && c < 256) v = (c < 128) ? w1s[k * 128 + c] : w1t[k * 128 + c - 128];
        sW1[idx] = __float2bfloat16(v);
    }
    for (int idx = tid; idx < 128 * W_LD; idx += NTHREADS) {
        int k = idx / W_LD, c = idx - k * W_LD;
        float v = 0.0f;
        if (c < 256) v = (c < 128) ? w2s[k * 128 + c] : w2t[k * 128 + c - 128];
        sW2[idx] = __float2bfloat16(v);
    }
    for (int idx = tid; idx < 128 * W3_LD; idx += NTHREADS) {
        int k = idx >> 4, c = idx & 15;
        float v = 0.0f;
        if (c < 2) v = w3s[k * 2 + c];
        else if (c >= 8 && c < 10) v = w3t[k * 2 + c - 8];
        sW3[idx] = __float2bfloat16(v);
    }
    for (int c = tid; c < 256; c += NTHREADS) {
        sB1[c] = (c < 128) ? b1s[c] : b1t[c - 128];
        sB2[c] = (c < 128) ? b2s[c] : b2t[c - 128];
    }
    if (tid < 4) sB3[tid] = (tid < 2) ? b3s[tid] : b3t[tid - 2];
    // zero xp pad cols [66,88) once (never rewritten)
    for (int idx = tid; idx < 128 * 22; idx += NTHREADS) {
        int r = idx / 22, c = 66 + (idx - r * 22);
        sXP[r * XP_LD + c] = __float2bfloat16(0.0f);
    }
    __syncthreads();

    const int warp = tid >> 5;
    const int lane = tid & 31;
    const int net  = warp >> 3;       // 0 = s-net (warps 0-7), 1 = t-net (8-15)
    const int R0   = (warp & 7) * 16; // row block shared by warp pair
    const int lg   = lane >> 3;       // ldmatrix group 0..3
    const int lr   = lane & 7;

    for (int tile = blockIdx.x; tile < NTILES; tile += gridDim.x) {
        __syncthreads();  // previous tile's epilogue reads of sXA/sST done
        const int base = tile * MTILE;

        // ---- build xp tile: cols[0..1]=x[keep], cols[2..65]=h, rest zero ----
        for (int idx = tid; idx < 128 * 16; idx += NTHREADS) {
            int r = idx >> 4, q = idx & 15;
            float4 hv = reinterpret_cast<const float4*>(h)[(base + r) * 16 + q];
            __nv_bfloat162* p =
                reinterpret_cast<__nv_bfloat162*>(&sXP[r * XP_LD + 2 + 4 * q]);
            p[0] = __floats2bfloat162_rn(hv.x, hv.y);
            p[1] = __floats2bfloat162_rn(hv.z, hv.w);
        }
        if (tid < 128) {
            int r = tid;
            float4 xv;
            if (FIRST) xv = reinterpret_cast<const float4*>(theta)[base + r];
            else       xv = reinterpret_cast<const float4*>(g_x)[base + r];
            reinterpret_cast<float4*>(sXA)[r] = xv;
            float xc[4] = {xv.x, xv.y, xv.z, xv.w};
            *reinterpret_cast<__nv_bfloat162*>(&sXP[r * XP_LD]) =
                __floats2bfloat162_rn(xc[K0], xc[K1]);
        }
        __syncthreads();

        // ---- GEMM1: A frags from xp (K=80), this warp's net only (128 cols) ----
        uint32_t axp[5][4];
        {
            int row = R0 + lr + (lg & 1) * 8;
            int colo = (lg >> 1) * 8;
            const __nv_bfloat16* pbase = &sXP[row * XP_LD + colo];
            #pragma unroll
            for (int ks = 0; ks < 5; ks++) {
                ldsm_x4(smem_u32(pbase + ks * 16),
                        axp[ks][0], axp[ks][1], axp[ks][2], axp[ks][3]);
            }
        }
        // hid1 kept as 8 A-fragments (K-local 0..127 of this net's half)
        uint32_t hf[8][4];
        #pragma unroll
        for (int ch = 0; ch < 2; ch++) {
            float acc[8][4] = {};
            #pragma unroll
            for (int ks = 0; ks < 5; ks++) {
                int krow = ks * 16 + lr + (lg & 1) * 8;
                int cb = net * 128 + ch * 64 + (lg >> 1) * 8;
                uint32_t bf[4][4];
                #pragma unroll
                for (int p = 0; p < 4; p++)
                    ldsm_x4t(smem_u32(&sW1[krow * W_LD + cb + p * 16]),
                             bf[p][0], bf[p][1], bf[p][2], bf[p][3]);
                #pragma unroll
                for (int p = 0; p < 4; p++) {
                    mma_bf16(acc[2 * p],     axp[ks], bf[p][0], bf[p][1]);
                    mma_bf16(acc[2 * p + 1], axp[ks], bf[p][2], bf[p][3]);
                }
            }
            #pragma unroll
            for (int j = 0; j < 8; j++) {
                int c = net * 128 + ch * 64 + j * 8 + (lane & 3) * 2;
                float2 bb = *reinterpret_cast<const float2*>(&sB1[c]);
                acc[j][0] = gelu(acc[j][0] + bb.x);
                acc[j][1] = gelu(acc[j][1] + bb.y);
                acc[j][2] = gelu(acc[j][2] + bb.x);
                acc[j][3] = gelu(acc[j][3] + bb.y);
            }
            #pragma unroll
            for (int kf = 0; kf < 4; kf++) {
                hf[ch * 4 + kf][0] = pack_bf2(acc[2 * kf][0], acc[2 * kf][1]);
                hf[ch * 4 + kf][1] = pack_bf2(acc[2 * kf][2], acc[2 * kf][3]);
                hf[ch * 4 + kf][2] = pack_bf2(acc[2 * kf + 1][0], acc[2 * kf + 1][1]);
                hf[ch * 4 + kf][3] = pack_bf2(acc[2 * kf + 1][2], acc[2 * kf + 1][3]);
            }
        }

        // ---- GEMM2 (+fused GEMM3), this warp's net ----
        float acc3[4] = {0.f, 0.f, 0.f, 0.f};
        #pragma unroll
        for (int cc = 0; cc < 2; cc++) {
            float acc[8][4] = {};
            #pragma unroll
            for (int ks = 0; ks < 8; ks++) {
                int krow = ks * 16 + lr + (lg & 1) * 8;
                int cb = net * 128 + cc * 64 + (lg >> 1) * 8;
                uint32_t bf[4][4];
                #pragma unroll
                for (int p = 0; p < 4; p++)
                    ldsm_x4t(smem_u32(&sW2[krow * W_LD + cb + p * 16]),
                             bf[p][0], bf[p][1], bf[p][2], bf[p][3]);
                const uint32_t* A = hf[ks];
                #pragma unroll
                for (int p = 0; p < 4; p++) {
                    mma_bf16(acc[2 * p],     A, bf[p][0], bf[p][1]);
                    mma_bf16(acc[2 * p + 1], A, bf[p][2], bf[p][3]);
                }
            }
            uint32_t af[4][4];
            #pragma unroll
            for (int j = 0; j < 8; j++) {
                int c = net * 128 + cc * 64 + j * 8 + (lane & 3) * 2;
                float2 bb = *reinterpret_cast<const float2*>(&sB2[c]);
                acc[j][0] = gelu(acc[j][0] + bb.x);
                acc[j][1] = gelu(acc[j][1] + bb.y);
                acc[j][2] = gelu(acc[j][2] + bb.x);
                acc[j][3] = gelu(acc[j][3] + bb.y);
            }
            #pragma unroll
            for (int kf = 0; kf < 4; kf++) {
                af[kf][0] = pack_bf2(acc[2 * kf][0], acc[2 * kf][1]);
                af[kf][1] = pack_bf2(acc[2 * kf][2], acc[2 * kf][3]);
                af[kf][2] = pack_bf2(acc[2 * kf + 1][0], acc[2 * kf + 1][1]);
                af[kf][3] = pack_bf2(acc[2 * kf + 1][2], acc[2 * kf + 1][3]);
            }
            // GEMM3 partial: hid2 chunk (K=64) x W3[net] (N=8, cols 0..1 valid)
            #pragma unroll
            for (int kf = 0; kf < 4; kf++) {
                int k0 = cc * 64 + kf * 16;
                uint32_t addr =
                    smem_u32(&sW3[(k0 + (lane & 15)) * W3_LD + net * 8]);
                uint32_t b0, b1;
                ldsm_x2t(addr, b0, b1);
                mma_bf16(acc3, af[kf], b0, b1);
            }
        }

        // ---- stage this net's (c0,c1) per row into smem ----
        if ((lane & 3) == 0) {
            int r1 = lane >> 2;
            #pragma unroll
            for (int half = 0; half < 2; half++) {
                int row = R0 + r1 + half * 8;
                sST[(net * 128 + row) * 2 + 0] = acc3[half * 2 + 0];
                sST[(net * 128 + row) * 2 + 1] = acc3[half * 2 + 1];
            }
        }
        __syncthreads();

        // ---- epilogue: one thread per row ----
        if (tid < 128) {
            int row = tid;
            int b = base + row;
            float s0 = sST[row * 2 + 0] + sB3[0];
            float s1 = sST[row * 2 + 1] + sB3[1];
            float t0 = sST[(128 + row) * 2 + 0] + sB3[2];
            float t1 = sST[(128 + row) * 2 + 1] + sB3[3];
            float4 xv = reinterpret_cast<const float4*>(sXA)[row];
            float xc[4] = {xv.x, xv.y, xv.z, xv.w};
            float nx0 = xc[T0] * __expf(s0) + t0;
            float nx1 = xc[T1] * __expf(s1) + t1;
            float ld = s0 + s1;
            if (!FIRST) ld += g_ld[b];
            xc[T0] = nx0;
            xc[T1] = nx1;
            if (!LAST) {
                reinterpret_cast<float4*>(g_x)[b] =
                    make_float4(xc[0], xc[1], xc[2], xc[3]);
                g_ld[b] = ld;
            } else {
                float ss = xc[0] * xc[0] + xc[1] * xc[1] +
                           xc[2] * xc[2] + xc[3] * xc[3];
                out[b] = -0.5f * ss - 3.6757541328186907f + ld;
            }
        }
    }
}

extern "C" void kernel_launch(void* const* d_in, const int* in_sizes, int n_in,
                              void* d_out, int out_size)
{
    const float* theta = (const float*)d_in[0];
    const float* h     = (const float*)d_in[1];
    const float* sW1   = (const float*)d_in[2];
    const float* sb1   = (const float*)d_in[3];
    const float* sW2   = (const float*)d_in[4];
    const float* sb2   = (const float*)d_in[5];
    const float* sW3   = (const float*)d_in[6];
    const float* sb3   = (const float*)d_in[7];
    const float* tW1   = (const float*)d_in[8];
    const float* tb1   = (const float*)d_in[9];
    const float* tW2   = (const float*)d_in[10];
    const float* tb2   = (const float*)d_in[11];
    const float* tW3   = (const float*)d_in[12];
    const float* tb3   = (const float*)d_in[13];
    float* out = (float*)d_out;

    int nsm = 148;
    cudaDeviceGetAttribute(&nsm, cudaDevAttrMultiProcessorCount, 0);

    cudaFuncSetAttribute(nvp_layer<0>, cudaFuncAttributeMaxDynamicSharedMemorySize, SMEM_BYTES);
    cudaFuncSetAttribute(nvp_layer<1>, cudaFuncAttributeMaxDynamicSharedMemorySize, SMEM_BYTES);
    cudaFuncSetAttribute(nvp_layer<2>, cudaFuncAttributeMaxDynamicSharedMemorySize, SMEM_BYTES);
    cudaFuncSetAttribute(nvp_layer<3>, cudaFuncAttributeMaxDynamicSharedMemorySize, SMEM_BYTES);

    dim3 grid(nsm), blk(NTHREADS);
    #define ARGS(L) theta, h,                                        \
        sW1 + (L) * 66 * 128, sb1 + (L) * 128,                       \
        sW2 + (L) * 128 * 128, sb2 + (L) * 128,                      \
        sW3 + (L) * 128 * 2, sb3 + (L) * 2,                          \
        tW1 + (L) * 66 * 128, tb1 + (L) * 128,                       \
        tW2 + (L) * 128 * 128, tb2 + (L) * 128,                      \
        tW3 + (L) * 128 * 2, tb3 + (L) * 2, out

    nvp_layer<0><<<grid, blk, SMEM_BYTES>>>(ARGS(0));
    nvp_layer<1><<<grid, blk, SMEM_BYTES>>>(ARGS(1));
    nvp_layer<2><<<grid, blk, SMEM_BYTES>>>(ARGS(2));
    nvp_layer<3><<<grid, blk, SMEM_BYTES>>>(ARGS(3));
    #undef ARGS
}

// round 7
// speedup vs baseline: 2.6643x; 1.0641x over previous
#include <cuda_runtime.h>
#include <cuda_bf16.h>
#include <cstdint>

// ---------------------------------------------------------------------------
// ConditionalRealNVP log_prob, fused per-layer passes with warp-level bf16 MMA.
//
// R6 vs R4 (tcgen05 is unavailable: harness PTX targets sm_103, no 'a'):
//   1. biases folded into MMA accumulator init (deletes 128 FADD/warp/tile)
//   2. GELU evaluated in packed bf16x2 (HMUL2/HFMA2 + tanh.approx.bf16x2)
//      after the pack that was needed anyway: 6 packed ops / 2 values vs
//      10 f32 ops / value. Epilogue was the largest instruction block.
// ---------------------------------------------------------------------------

#define BTOT   524288
#define MTILE  128
#define NTILES (BTOT / MTILE)   // 4096
#define XP_LD  88               // 66 used, pad->88 (conflict-free ldmatrix)
#define W_LD   264              // 256 used, pad->264 (conflict-free)
#define W3_LD  16

// smem byte offsets (all 16B aligned)
#define OFF_W1  0                         // 80*264*2  = 42240
#define OFF_W2  42240                     // 128*264*2 = 67584
#define OFF_W3  109824                    // 128*16*2  = 4096
#define OFF_XP  113920                    // 128*88*2  = 22528
#define OFF_XA  136448                    // 128*4*4   = 2048
#define OFF_B1  138496                    // 256*4     = 1024
#define OFF_B2  139520                    // 256*4     = 1024
#define OFF_B3  140544                    // 4*4       = 16
#define OFF_ST  140560                    // 2*128*2*4 = 2048 (s/t staging)
#define SMEM_BYTES 142608

#define NTHREADS 512

__device__ float g_x[BTOT * 4];
__device__ float g_ld[BTOT];

__device__ __forceinline__ uint32_t smem_u32(const void* p) {
    return static_cast<uint32_t>(__cvta_generic_to_shared(p));
}
__device__ __forceinline__ void ldsm_x4(uint32_t a, uint32_t& r0, uint32_t& r1,
                                        uint32_t& r2, uint32_t& r3) {
    asm volatile("ldmatrix.sync.aligned.m8n8.x4.shared.b16 {%0,%1,%2,%3},[%4];"
                 : "=r"(r0), "=r"(r1), "=r"(r2), "=r"(r3) : "r"(a));
}
__device__ __forceinline__ void ldsm_x4t(uint32_t a, uint32_t& r0, uint32_t& r1,
                                         uint32_t& r2, uint32_t& r3) {
    asm volatile("ldmatrix.sync.aligned.m8n8.x4.trans.shared.b16 {%0,%1,%2,%3},[%4];"
                 : "=r"(r0), "=r"(r1), "=r"(r2), "=r"(r3) : "r"(a));
}
__device__ __forceinline__ void ldsm_x2t(uint32_t a, uint32_t& r0, uint32_t& r1) {
    asm volatile("ldmatrix.sync.aligned.m8n8.x2.trans.shared.b16 {%0,%1},[%2];"
                 : "=r"(r0), "=r"(r1) : "r"(a));
}
__device__ __forceinline__ void mma_bf16(float* c, const uint32_t* a,
                                         uint32_t b0, uint32_t b1) {
    asm volatile(
        "mma.sync.aligned.m16n8k16.row.col.f32.bf16.bf16.f32 "
        "{%0,%1,%2,%3},{%4,%5,%6,%7},{%8,%9},{%0,%1,%2,%3};"
        : "+f"(c[0]), "+f"(c[1]), "+f"(c[2]), "+f"(c[3])
        : "r"(a[0]), "r"(a[1]), "r"(a[2]), "r"(a[3]), "r"(b0), "r"(b1));
}
__device__ __forceinline__ uint32_t pack_bf2(float lo, float hi) {
    __nv_bfloat162 v = __floats2bfloat162_rn(lo, hi);
    return *reinterpret_cast<uint32_t*>(&v);
}
// packed bf16x2 tanh-approx GELU: 0.5x(1+tanh(0.79788456*(x+0.044715x^3)))
__device__ __forceinline__ uint32_t gelu2(uint32_t xin) {
    __nv_bfloat162 x = *reinterpret_cast<__nv_bfloat162*>(&xin);
    const __nv_bfloat162 c1 = __floats2bfloat162_rn(0.035677408136f, 0.035677408136f);
    const __nv_bfloat162 c0 = __floats2bfloat162_rn(0.7978845608028654f, 0.7978845608028654f);
    const __nv_bfloat162 hf = __floats2bfloat162_rn(0.5f, 0.5f);
    __nv_bfloat162 x2 = __hmul2(x, x);
    __nv_bfloat162 w  = __hfma2(x2, c1, c0);
    __nv_bfloat162 u  = __hmul2(x, w);
    uint32_t th;
    asm("tanh.approx.bf16x2 %0, %1;"
        : "=r"(th) : "r"(*reinterpret_cast<uint32_t*>(&u)));
    __nv_bfloat162 hx = __hmul2(x, hf);
    __nv_bfloat162 r  = __hfma2(hx, *reinterpret_cast<__nv_bfloat162*>(&th), hx);
    return *reinterpret_cast<uint32_t*>(&r);
}

template <int LYR>
__global__ void __launch_bounds__(NTHREADS, 1)
nvp_layer(const float* __restrict__ theta, const float* __restrict__ h,
          const float* __restrict__ w1s, const float* __restrict__ b1s,
          const float* __restrict__ w2s, const float* __restrict__ b2s,
          const float* __restrict__ w3s, const float* __restrict__ b3s,
          const float* __restrict__ w1t, const float* __restrict__ b1t,
          const float* __restrict__ w2t, const float* __restrict__ b2t,
          const float* __restrict__ w3t, const float* __restrict__ b3t,
          float* __restrict__ out)
{
    constexpr bool FIRST = (LYR == 0);
    constexpr bool LAST  = (LYR == 3);
    // KEEP = ((0,1),(1,2),(2,3),(0,3)); TRANS = ((2,3),(0,3),(0,1),(1,2))
    constexpr int K0 = (LYR == 0) ? 0 : (LYR == 1) ? 1 : (LYR == 2) ? 2 : 0;
    constexpr int K1 = (LYR == 0) ? 1 : (LYR == 1) ? 2 : (LYR == 2) ? 3 : 3;
    constexpr int T0 = (LYR == 0) ? 2 : (LYR == 1) ? 0 : (LYR == 2) ? 0 : 1;
    constexpr int T1 = (LYR == 0) ? 3 : (LYR == 1) ? 3 : (LYR == 2) ? 1 : 2;

    extern __shared__ char smem[];
    __nv_bfloat16* sW1 = reinterpret_cast<__nv_bfloat16*>(smem + OFF_W1);
    __nv_bfloat16* sW2 = reinterpret_cast<__nv_bfloat16*>(smem + OFF_W2);
    __nv_bfloat16* sW3 = reinterpret_cast<__nv_bfloat16*>(smem + OFF_W3);
    __nv_bfloat16* sXP = reinterpret_cast<__nv_bfloat16*>(smem + OFF_XP);
    float* sXA = reinterpret_cast<float*>(smem + OFF_XA);
    float* sB1 = reinterpret_cast<float*>(smem + OFF_B1);
    float* sB2 = reinterpret_cast<float*>(smem + OFF_B2);
    float* sB3 = reinterpret_cast<float*>(smem + OFF_B3);
    float* sST = reinterpret_cast<float*>(smem + OFF_ST);  // [2][128][2]

    const int tid = threadIdx.x;

    // ---- one-time per block: weights -> smem (bf16, s|t combined, padded) ----
    for (int idx = tid; idx < 80 * W_LD; idx += NTHREADS) {
        int k = idx / W_LD, c = idx - k * W_LD;
        float v = 0.0f;
        if (k < 66 && c < 256) v = (c < 128) ? w1s[k * 128 + c] : w1t[k * 128 + c - 128];
        sW1[idx] = __float2bfloat16(v);
    }
    for (int idx = tid; idx < 128 * W_LD; idx += NTHREADS) {
        int k = idx / W_LD, c = idx - k * W_LD;
        float v = 0.0f;
        if (c < 256) v = (c < 128) ? w2s[k * 128 + c] : w2t[k * 128 + c - 128];
        sW2[idx] = __float2bfloat16(v);
    }
    for (int idx = tid; idx < 128 * W3_LD; idx += NTHREADS) {
        int k = idx >> 4, c = idx & 15;
        float v = 0.0f;
        if (c < 2) v = w3s[k * 2 + c];
        else if (c >= 8 && c < 10) v = w3t[k * 2 + c - 8];
        sW3[idx] = __float2bfloat16(v);
    }
    for (int c = tid; c < 256; c += NTHREADS) {
        sB1[c] = (c < 128) ? b1s[c] : b1t[c - 128];
        sB2[c] = (c < 128) ? b2s[c] : b2t[c - 128];
    }
    if (tid < 4) sB3[tid] = (tid < 2) ? b3s[tid] : b3t[tid - 2];
    // zero xp pad cols [66,88) once (never rewritten)
    for (int idx = tid; idx < 128 * 22; idx += NTHREADS) {
        int r = idx / 22, c = 66 + (idx - r * 22);
        sXP[r * XP_LD + c] = __float2bfloat16(0.0f);
    }
    __syncthreads();

    const int warp = tid >> 5;
    const int lane = tid & 31;
    const int net  = warp >> 3;       // 0 = s-net (warps 0-7), 1 = t-net (8-15)
    const int R0   = (warp & 7) * 16; // row block shared by warp pair
    const int lg   = lane >> 3;       // ldmatrix group 0..3
    const int lr   = lane & 7;

    for (int tile = blockIdx.x; tile < NTILES; tile += gridDim.x) {
        __syncthreads();  // previous tile's epilogue reads of sXA/sST done
        const int base = tile * MTILE;

        // ---- build xp tile: cols[0..1]=x[keep], cols[2..65]=h, rest zero ----
        for (int idx = tid; idx < 128 * 16; idx += NTHREADS) {
            int r = idx >> 4, q = idx & 15;
            float4 hv = reinterpret_cast<const float4*>(h)[(base + r) * 16 + q];
            __nv_bfloat162* p =
                reinterpret_cast<__nv_bfloat162*>(&sXP[r * XP_LD + 2 + 4 * q]);
            p[0] = __floats2bfloat162_rn(hv.x, hv.y);
            p[1] = __floats2bfloat162_rn(hv.z, hv.w);
        }
        if (tid < 128) {
            int r = tid;
            float4 xv;
            if (FIRST) xv = reinterpret_cast<const float4*>(theta)[base + r];
            else       xv = reinterpret_cast<const float4*>(g_x)[base + r];
            reinterpret_cast<float4*>(sXA)[r] = xv;
            float xc[4] = {xv.x, xv.y, xv.z, xv.w};
            *reinterpret_cast<__nv_bfloat162*>(&sXP[r * XP_LD]) =
                __floats2bfloat162_rn(xc[K0], xc[K1]);
        }
        __syncthreads();

        // ---- GEMM1: A frags from xp (K=80), this warp's net only (128 cols) ----
        uint32_t axp[5][4];
        {
            int row = R0 + lr + (lg & 1) * 8;
            int colo = (lg >> 1) * 8;
            const __nv_bfloat16* pbase = &sXP[row * XP_LD + colo];
            #pragma unroll
            for (int ks = 0; ks < 5; ks++) {
                ldsm_x4(smem_u32(pbase + ks * 16),
                        axp[ks][0], axp[ks][1], axp[ks][2], axp[ks][3]);
            }
        }
        // hid1 kept as 8 A-fragments (K-local 0..127 of this net's half)
        uint32_t hf[8][4];
        #pragma unroll
        for (int ch = 0; ch < 2; ch++) {
            float acc[8][4];
            #pragma unroll
            for (int j = 0; j < 8; j++) {   // bias folded into acc init
                int c = net * 128 + ch * 64 + j * 8 + (lane & 3) * 2;
                float2 bb = *reinterpret_cast<const float2*>(&sB1[c]);
                acc[j][0] = bb.x; acc[j][1] = bb.y;
                acc[j][2] = bb.x; acc[j][3] = bb.y;
            }
            #pragma unroll
            for (int ks = 0; ks < 5; ks++) {
                int krow = ks * 16 + lr + (lg & 1) * 8;
                int cb = net * 128 + ch * 64 + (lg >> 1) * 8;
                uint32_t bf[4][4];
                #pragma unroll
                for (int p = 0; p < 4; p++)
                    ldsm_x4t(smem_u32(&sW1[krow * W_LD + cb + p * 16]),
                             bf[p][0], bf[p][1], bf[p][2], bf[p][3]);
                #pragma unroll
                for (int p = 0; p < 4; p++) {
                    mma_bf16(acc[2 * p],     axp[ks], bf[p][0], bf[p][1]);
                    mma_bf16(acc[2 * p + 1], axp[ks], bf[p][2], bf[p][3]);
                }
            }
            #pragma unroll
            for (int kf = 0; kf < 4; kf++) {   // pack then packed GELU
                hf[ch * 4 + kf][0] = gelu2(pack_bf2(acc[2 * kf][0], acc[2 * kf][1]));
                hf[ch * 4 + kf][1] = gelu2(pack_bf2(acc[2 * kf][2], acc[2 * kf][3]));
                hf[ch * 4 + kf][2] = gelu2(pack_bf2(acc[2 * kf + 1][0], acc[2 * kf + 1][1]));
                hf[ch * 4 + kf][3] = gelu2(pack_bf2(acc[2 * kf + 1][2], acc[2 * kf + 1][3]));
            }
        }

        // ---- GEMM2 (+fused GEMM3), this warp's net ----
        float acc3[4] = {0.f, 0.f, 0.f, 0.f};
        #pragma unroll
        for (int cc = 0; cc < 2; cc++) {
            float acc[8][4];
            #pragma unroll
            for (int j = 0; j < 8; j++) {   // bias folded into acc init
                int c = net * 128 + cc * 64 + j * 8 + (lane & 3) * 2;
                float2 bb = *reinterpret_cast<const float2*>(&sB2[c]);
                acc[j][0] = bb.x; acc[j][1] = bb.y;
                acc[j][2] = bb.x; acc[j][3] = bb.y;
            }
            #pragma unroll
            for (int ks = 0; ks < 8; ks++) {
                int krow = ks * 16 + lr + (lg & 1) * 8;
                int cb = net * 128 + cc * 64 + (lg >> 1) * 8;
                uint32_t bf[4][4];
                #pragma unroll
                for (int p = 0; p < 4; p++)
                    ldsm_x4t(smem_u32(&sW2[krow * W_LD + cb + p * 16]),
                             bf[p][0], bf[p][1], bf[p][2], bf[p][3]);
                const uint32_t* A = hf[ks];
                #pragma unroll
                for (int p = 0; p < 4; p++) {
                    mma_bf16(acc[2 * p],     A, bf[p][0], bf[p][1]);
                    mma_bf16(acc[2 * p + 1], A, bf[p][2], bf[p][3]);
                }
            }
            uint32_t af[4][4];
            #pragma unroll
            for (int kf = 0; kf < 4; kf++) {
                af[kf][0] = gelu2(pack_bf2(acc[2 * kf][0], acc[2 * kf][1]));
                af[kf][1] = gelu2(pack_bf2(acc[2 * kf][2], acc[2 * kf][3]));
                af[kf][2] = gelu2(pack_bf2(acc[2 * kf + 1][0], acc[2 * kf + 1][1]));
                af[kf][3] = gelu2(pack_bf2(acc[2 * kf + 1][2], acc[2 * kf + 1][3]));
            }
            // GEMM3 partial: hid2 chunk (K=64) x W3[net] (N=8, cols 0..1 valid)
            #pragma unroll
            for (int kf = 0; kf < 4; kf++) {
                int k0 = cc * 64 + kf * 16;
                uint32_t addr =
                    smem_u32(&sW3[(k0 + (lane & 15)) * W3_LD + net * 8]);
                uint32_t b0, b1;
                ldsm_x2t(addr, b0, b1);
                mma_bf16(acc3, af[kf], b0, b1);
            }
        }

        // ---- stage this net's (c0,c1) per row into smem ----
        if ((lane & 3) == 0) {
            int r1 = lane >> 2;
            #pragma unroll
            for (int half = 0; half < 2; half++) {
                int row = R0 + r1 + half * 8;
                sST[(net * 128 + row) * 2 + 0] = acc3[half * 2 + 0];
                sST[(net * 128 + row) * 2 + 1] = acc3[half * 2 + 1];
            }
        }
        __syncthreads();

        // ---- epilogue: one thread per row ----
        if (tid < 128) {
            int row = tid;
            int b = base + row;
            float s0 = sST[row * 2 + 0] + sB3[0];
            float s1 = sST[row * 2 + 1] + sB3[1];
            float t0 = sST[(128 + row) * 2 + 0] + sB3[2];
            float t1 = sST[(128 + row) * 2 + 1] + sB3[3];
            float4 xv = reinterpret_cast<const float4*>(sXA)[row];
            float xc[4] = {xv.x, xv.y, xv.z, xv.w};
            float nx0 = xc[T0] * __expf(s0) + t0;
            float nx1 = xc[T1] * __expf(s1) + t1;
            float ld = s0 + s1;
            if (!FIRST) ld += g_ld[b];
            xc[T0] = nx0;
            xc[T1] = nx1;
            if (!LAST) {
                reinterpret_cast<float4*>(g_x)[b] =
                    make_float4(xc[0], xc[1], xc[2], xc[3]);
                g_ld[b] = ld;
            } else {
                float ss = xc[0] * xc[0] + xc[1] * xc[1] +
                           xc[2] * xc[2] + xc[3] * xc[3];
                out[b] = -0.5f * ss - 3.6757541328186907f + ld;
            }
        }
    }
}

extern "C" void kernel_launch(void* const* d_in, const int* in_sizes, int n_in,
                              void* d_out, int out_size)
{
    const float* theta = (const float*)d_in[0];
    const float* h     = (const float*)d_in[1];
    const float* sW1   = (const float*)d_in[2];
    const float* sb1   = (const float*)d_in[3];
    const float* sW2   = (const float*)d_in[4];
    const float* sb2   = (const float*)d_in[5];
    const float* sW3   = (const float*)d_in[6];
    const float* sb3   = (const float*)d_in[7];
    const float* tW1   = (const float*)d_in[8];
    const float* tb1   = (const float*)d_in[9];
    const float* tW2   = (const float*)d_in[10];
    const float* tb2   = (const float*)d_in[11];
    const float* tW3   = (const float*)d_in[12];
    const float* tb3   = (const float*)d_in[13];
    float* out = (float*)d_out;

    int nsm = 148;
    cudaDeviceGetAttribute(&nsm, cudaDevAttrMultiProcessorCount, 0);

    cudaFuncSetAttribute(nvp_layer<0>, cudaFuncAttributeMaxDynamicSharedMemorySize, SMEM_BYTES);
    cudaFuncSetAttribute(nvp_layer<1>, cudaFuncAttributeMaxDynamicSharedMemorySize, SMEM_BYTES);
    cudaFuncSetAttribute(nvp_layer<2>, cudaFuncAttributeMaxDynamicSharedMemorySize, SMEM_BYTES);
    cudaFuncSetAttribute(nvp_layer<3>, cudaFuncAttributeMaxDynamicSharedMemorySize, SMEM_BYTES);

    dim3 grid(nsm), blk(NTHREADS);
    #define ARGS(L) theta, h,                                        \
        sW1 + (L) * 66 * 128, sb1 + (L) * 128,                       \
        sW2 + (L) * 128 * 128, sb2 + (L) * 128,                      \
        sW3 + (L) * 128 * 2, sb3 + (L) * 2,                          \
        tW1 + (L) * 66 * 128, tb1 + (L) * 128,                       \
        tW2 + (L) * 128 * 128, tb2 + (L) * 128,                      \
        tW3 + (L) * 128 * 2, tb3 + (L) * 2, out

    nvp_layer<0><<<grid, blk, SMEM_BYTES>>>(ARGS(0));
    nvp_layer<1><<<grid, blk, SMEM_BYTES>>>(ARGS(1));
    nvp_layer<2><<<grid, blk, SMEM_BYTES>>>(ARGS(2));
    nvp_layer<3><<<grid, blk, SMEM_BYTES>>>(ARGS(3));
    #undef ARGS
}

// round 8
// speedup vs baseline: 3.4419x; 1.2919x over previous
#include <cuda_runtime.h>
#include <cuda_bf16.h>
#include <cstdint>

// ---------------------------------------------------------------------------
// ConditionalRealNVP log_prob — R7.
//   1. h pre-converted to bf16 once (g_hbf) by a small pre-kernel.
//   2. cp.async double-buffered xp/x tile prefetch (global latency hidden).
//   3. Explicit sw-pipelined weight-fragment loads (bfa/bfb alternation).
// xp layout: cols 0..63 = h, cols 64..65 = x[keep], 66..87 = zero pad.
// ---------------------------------------------------------------------------

#define BTOT   524288
#define MTILE  128
#define NTILES (BTOT / MTILE)   // 4096
#define XP_LD  88
#define W_LD   264
#define W3_LD  16
#define NTHREADS 512
#define XP_BYTES (128 * XP_LD * 2)   // 22528

// smem byte offsets
#define OFF_W1  0                  // 80*264*2  = 42240
#define OFF_W2  42240              // 128*264*2 = 67584
#define OFF_W3  109824             // 128*16*2  = 4096
#define OFF_XP  113920             // 2 x 22528 = 45056
#define OFF_XA  158976             // 2 x 2048  = 4096
#define OFF_B1  163072             // 1024
#define OFF_B2  164096             // 1024
#define OFF_B3  165120             // 32
#define OFF_ST  165152             // 2 x 2048  = 4096
#define SMEM_BYTES 169248

__device__ float g_x[BTOT * 4];
__device__ float g_ld[BTOT];
__device__ __nv_bfloat16 g_hbf[(long)BTOT * 64];

__device__ __forceinline__ uint32_t smem_u32(const void* p) {
    return static_cast<uint32_t>(__cvta_generic_to_shared(p));
}
__device__ __forceinline__ void cp_async16(uint32_t dst, const void* src) {
    asm volatile("cp.async.cg.shared.global [%0], [%1], 16;"
                 :: "r"(dst), "l"(src) : "memory");
}
#define CP_COMMIT() asm volatile("cp.async.commit_group;" ::: "memory")
#define CP_WAIT0()  asm volatile("cp.async.wait_group 0;" ::: "memory")

__device__ __forceinline__ void ldsm_x4(uint32_t a, uint32_t& r0, uint32_t& r1,
                                        uint32_t& r2, uint32_t& r3) {
    asm volatile("ldmatrix.sync.aligned.m8n8.x4.shared.b16 {%0,%1,%2,%3},[%4];"
                 : "=r"(r0), "=r"(r1), "=r"(r2), "=r"(r3) : "r"(a));
}
__device__ __forceinline__ void ldsm_x4t(uint32_t a, uint32_t& r0, uint32_t& r1,
                                         uint32_t& r2, uint32_t& r3) {
    asm volatile("ldmatrix.sync.aligned.m8n8.x4.trans.shared.b16 {%0,%1,%2,%3},[%4];"
                 : "=r"(r0), "=r"(r1), "=r"(r2), "=r"(r3) : "r"(a));
}
__device__ __forceinline__ void ldsm_x2t(uint32_t a, uint32_t& r0, uint32_t& r1) {
    asm volatile("ldmatrix.sync.aligned.m8n8.x2.trans.shared.b16 {%0,%1},[%2];"
                 : "=r"(r0), "=r"(r1) : "r"(a));
}
__device__ __forceinline__ void mma_bf16(float* c, const uint32_t* a,
                                         uint32_t b0, uint32_t b1) {
    asm volatile(
        "mma.sync.aligned.m16n8k16.row.col.f32.bf16.bf16.f32 "
        "{%0,%1,%2,%3},{%4,%5,%6,%7},{%8,%9},{%0,%1,%2,%3};"
        : "+f"(c[0]), "+f"(c[1]), "+f"(c[2]), "+f"(c[3])
        : "r"(a[0]), "r"(a[1]), "r"(a[2]), "r"(a[3]), "r"(b0), "r"(b1));
}
__device__ __forceinline__ uint32_t pack_bf2(float lo, float hi) {
    __nv_bfloat162 v = __floats2bfloat162_rn(lo, hi);
    return *reinterpret_cast<uint32_t*>(&v);
}
// packed bf16x2 tanh-approx GELU
__device__ __forceinline__ uint32_t gelu2(uint32_t xin) {
    __nv_bfloat162 x = *reinterpret_cast<__nv_bfloat162*>(&xin);
    const __nv_bfloat162 c1 = __floats2bfloat162_rn(0.035677408136f, 0.035677408136f);
    const __nv_bfloat162 c0 = __floats2bfloat162_rn(0.7978845608028654f, 0.7978845608028654f);
    const __nv_bfloat162 hf = __floats2bfloat162_rn(0.5f, 0.5f);
    __nv_bfloat162 x2 = __hmul2(x, x);
    __nv_bfloat162 w  = __hfma2(x2, c1, c0);
    __nv_bfloat162 u  = __hmul2(x, w);
    uint32_t th;
    asm("tanh.approx.bf16x2 %0, %1;"
        : "=r"(th) : "r"(*reinterpret_cast<uint32_t*>(&u)));
    __nv_bfloat162 hx = __hmul2(x, hf);
    __nv_bfloat162 r  = __hfma2(hx, *reinterpret_cast<__nv_bfloat162*>(&th), hx);
    return *reinterpret_cast<uint32_t*>(&r);
}

__device__ __forceinline__ void ldB4(const __nv_bfloat16* p, uint32_t bf[4][4]) {
    #pragma unroll
    for (int q = 0; q < 4; q++)
        ldsm_x4t(smem_u32(p + q * 16), bf[q][0], bf[q][1], bf[q][2], bf[q][3]);
}
__device__ __forceinline__ void mma8(float acc[8][4], const uint32_t* A,
                                     uint32_t bf[4][4]) {
    #pragma unroll
    for (int q = 0; q < 4; q++) {
        mma_bf16(acc[2 * q],     A, bf[q][0], bf[q][1]);
        mma_bf16(acc[2 * q + 1], A, bf[q][2], bf[q][3]);
    }
}

// ---- pre-pass: h fp32 -> bf16 (run once per graph replay) ----
__global__ void __launch_bounds__(256)
cvt_h_kernel(const float* __restrict__ h) {
    long i = ((long)blockIdx.x * 256 + threadIdx.x) * 8;
    float4 a = *reinterpret_cast<const float4*>(h + i);
    float4 b = *reinterpret_cast<const float4*>(h + i + 4);
    uint4 o;
    o.x = pack_bf2(a.x, a.y); o.y = pack_bf2(a.z, a.w);
    o.z = pack_bf2(b.x, b.y); o.w = pack_bf2(b.z, b.w);
    *reinterpret_cast<uint4*>(g_hbf + i) = o;
}

template <int LYR>
__global__ void __launch_bounds__(NTHREADS, 1)
nvp_layer(const float* __restrict__ theta, const float* __restrict__ h,
          const float* __restrict__ w1s, const float* __restrict__ b1s,
          const float* __restrict__ w2s, const float* __restrict__ b2s,
          const float* __restrict__ w3s, const float* __restrict__ b3s,
          const float* __restrict__ w1t, const float* __restrict__ b1t,
          const float* __restrict__ w2t, const float* __restrict__ b2t,
          const float* __restrict__ w3t, const float* __restrict__ b3t,
          float* __restrict__ out)
{
    constexpr bool FIRST = (LYR == 0);
    constexpr bool LAST  = (LYR == 3);
    // KEEP = ((0,1),(1,2),(2,3),(0,3)); TRANS = ((2,3),(0,3),(0,1),(1,2))
    constexpr int K0 = (LYR == 0) ? 0 : (LYR == 1) ? 1 : (LYR == 2) ? 2 : 0;
    constexpr int K1 = (LYR == 0) ? 1 : (LYR == 1) ? 2 : (LYR == 2) ? 3 : 3;
    constexpr int T0 = (LYR == 0) ? 2 : (LYR == 1) ? 0 : (LYR == 2) ? 0 : 1;
    constexpr int T1 = (LYR == 0) ? 3 : (LYR == 1) ? 3 : (LYR == 2) ? 1 : 2;

    extern __shared__ char smem[];
    const uint32_t smem_base = smem_u32(smem);
    __nv_bfloat16* sW1 = reinterpret_cast<__nv_bfloat16*>(smem + OFF_W1);
    __nv_bfloat16* sW2 = reinterpret_cast<__nv_bfloat16*>(smem + OFF_W2);
    __nv_bfloat16* sW3 = reinterpret_cast<__nv_bfloat16*>(smem + OFF_W3);
    float* sB1 = reinterpret_cast<float*>(smem + OFF_B1);
    float* sB2 = reinterpret_cast<float*>(smem + OFF_B2);
    float* sB3 = reinterpret_cast<float*>(smem + OFF_B3);

    const int tid = threadIdx.x;

    // ---- one-time weights -> smem ----
    // W1 rows: 0..63 = w1[k+2] (h part), 64..65 = w1[0..1] (x-keep), 66..79 = 0
    for (int idx = tid; idx < 80 * W_LD; idx += NTHREADS) {
        int k = idx / W_LD, c = idx - k * W_LD;
        float v = 0.0f;
        if (c < 256) {
            const float* w1 = (c < 128) ? w1s : w1t;
            int cc = c & 127;
            if (k < 64)      v = w1[(k + 2) * 128 + cc];
            else if (k < 66) v = w1[(k - 64) * 128 + cc];
        }
        sW1[idx] = __float2bfloat16(v);
    }
    for (int idx = tid; idx < 128 * W_LD; idx += NTHREADS) {
        int k = idx / W_LD, c = idx - k * W_LD;
        float v = 0.0f;
        if (c < 256) v = (c < 128) ? w2s[k * 128 + c] : w2t[k * 128 + c - 128];
        sW2[idx] = __float2bfloat16(v);
    }
    for (int idx = tid; idx < 128 * W3_LD; idx += NTHREADS) {
        int k = idx >> 4, c = idx & 15;
        float v = 0.0f;
        if (c < 2) v = w3s[k * 2 + c];
        else if (c >= 8 && c < 10) v = w3t[k * 2 + c - 8];
        sW3[idx] = __float2bfloat16(v);
    }
    for (int c = tid; c < 256; c += NTHREADS) {
        sB1[c] = (c < 128) ? b1s[c] : b1t[c - 128];
        sB2[c] = (c < 128) ? b2s[c] : b2t[c - 128];
    }
    if (tid < 4) sB3[tid] = (tid < 2) ? b3s[tid] : b3t[tid - 2];
    // zero xp pad cols [66,88) in BOTH buffers (never rewritten)
    for (int idx = tid; idx < 2 * 128 * 22; idx += NTHREADS) {
        int bufr = idx / 22, c = 66 + (idx - bufr * 22);
        int bb = bufr >> 7, r = bufr & 127;
        *reinterpret_cast<__nv_bfloat16*>(
            smem + OFF_XP + bb * XP_BYTES + (r * XP_LD + c) * 2) =
            __float2bfloat16(0.0f);
    }

    const int warp = tid >> 5;
    const int lane = tid & 31;
    const int net  = warp >> 3;
    const int R0   = (warp & 7) * 16;
    const int lg   = lane >> 3;
    const int lr   = lane & 7;

    // ---- prologue: prefetch tile0 into buf 0 ----
    const int tile0 = blockIdx.x;
    {
        const __nv_bfloat16* hsrc = g_hbf + (long)tile0 * MTILE * 64;
        uint32_t xpn = smem_base + OFF_XP;
        #pragma unroll
        for (int c = tid; c < 1024; c += NTHREADS) {
            int r = c >> 3, q = c & 7;
            cp_async16(xpn + r * 176 + q * 16, hsrc + r * 64 + q * 8);
        }
        if (tid < 128) {
            const float* xsrc = FIRST ? (theta + (long)(tile0 * MTILE + tid) * 4)
                                      : (g_x + (long)(tile0 * MTILE + tid) * 4);
            cp_async16(smem_base + OFF_XA + tid * 16, xsrc);
        }
        CP_COMMIT();
        CP_WAIT0();
        if (tid < 128) {
            float4 nx = *reinterpret_cast<float4*>(smem + OFF_XA + tid * 16);
            float c4[4] = {nx.x, nx.y, nx.z, nx.w};
            *reinterpret_cast<__nv_bfloat162*>(smem + OFF_XP + tid * 176 + 128) =
                __floats2bfloat162_rn(c4[K0], c4[K1]);
        }
    }
    __syncthreads();

    int buf = 0;
    for (int tile = tile0; tile < NTILES; tile += gridDim.x) {
        const int base = tile * MTILE;
        const int nt = tile + gridDim.x;
        const bool has_next = (nt < NTILES);

        // ---- prefetch next tile into buf^1 ----
        if (has_next) {
            const __nv_bfloat16* hsrc = g_hbf + (long)nt * MTILE * 64;
            uint32_t xpn = smem_base + OFF_XP + (buf ^ 1) * XP_BYTES;
            #pragma unroll
            for (int c = tid; c < 1024; c += NTHREADS) {
                int r = c >> 3, q = c & 7;
                cp_async16(xpn + r * 176 + q * 16, hsrc + r * 64 + q * 8);
            }
            if (tid < 128) {
                const float* xsrc = FIRST ? (theta + (long)(nt * MTILE + tid) * 4)
                                          : (g_x + (long)(nt * MTILE + tid) * 4);
                cp_async16(smem_base + OFF_XA + (buf ^ 1) * 2048 + tid * 16, xsrc);
            }
            CP_COMMIT();
        }

        __nv_bfloat16* sXP = reinterpret_cast<__nv_bfloat16*>(
            smem + OFF_XP + buf * XP_BYTES);
        float* sST = reinterpret_cast<float*>(smem + OFF_ST + buf * 2048);

        // ---- GEMM1: A frags from xp (K=80) ----
        uint32_t axp[5][4];
        {
            int row = R0 + lr + (lg & 1) * 8;
            int colo = (lg >> 1) * 8;
            const __nv_bfloat16* pbase = &sXP[row * XP_LD + colo];
            #pragma unroll
            for (int ks = 0; ks < 5; ks++) {
                ldsm_x4(smem_u32(pbase + ks * 16),
                        axp[ks][0], axp[ks][1], axp[ks][2], axp[ks][3]);
            }
        }
        uint32_t hfr[8][4];
        #pragma unroll
        for (int ch = 0; ch < 2; ch++) {
            float acc[8][4];
            #pragma unroll
            for (int j = 0; j < 8; j++) {
                int c = net * 128 + ch * 64 + j * 8 + (lane & 3) * 2;
                float2 bb = *reinterpret_cast<const float2*>(&sB1[c]);
                acc[j][0] = bb.x; acc[j][1] = bb.y;
                acc[j][2] = bb.x; acc[j][3] = bb.y;
            }
            const __nv_bfloat16* wb =
                &sW1[(lr + (lg & 1) * 8) * W_LD + net * 128 + ch * 64 + (lg >> 1) * 8];
            uint32_t bfa[4][4], bfb[4][4];
            ldB4(wb, bfa);
            ldB4(wb + 16 * W_LD, bfb);  mma8(acc, axp[0], bfa);
            ldB4(wb + 32 * W_LD, bfa);  mma8(acc, axp[1], bfb);
            ldB4(wb + 48 * W_LD, bfb);  mma8(acc, axp[2], bfa);
            ldB4(wb + 64 * W_LD, bfa);  mma8(acc, axp[3], bfb);
                                        mma8(acc, axp[4], bfa);
            #pragma unroll
            for (int kf = 0; kf < 4; kf++) {
                hfr[ch * 4 + kf][0] = gelu2(pack_bf2(acc[2 * kf][0], acc[2 * kf][1]));
                hfr[ch * 4 + kf][1] = gelu2(pack_bf2(acc[2 * kf][2], acc[2 * kf][3]));
                hfr[ch * 4 + kf][2] = gelu2(pack_bf2(acc[2 * kf + 1][0], acc[2 * kf + 1][1]));
                hfr[ch * 4 + kf][3] = gelu2(pack_bf2(acc[2 * kf + 1][2], acc[2 * kf + 1][3]));
            }
        }

        // ---- GEMM2 (+fused GEMM3) ----
        float acc3[4] = {0.f, 0.f, 0.f, 0.f};
        #pragma unroll
        for (int cc = 0; cc < 2; cc++) {
            float acc[8][4];
            #pragma unroll
            for (int j = 0; j < 8; j++) {
                int c = net * 128 + cc * 64 + j * 8 + (lane & 3) * 2;
                float2 bb = *reinterpret_cast<const float2*>(&sB2[c]);
                acc[j][0] = bb.x; acc[j][1] = bb.y;
                acc[j][2] = bb.x; acc[j][3] = bb.y;
            }
            const __nv_bfloat16* wb =
                &sW2[(lr + (lg & 1) * 8) * W_LD + net * 128 + cc * 64 + (lg >> 1) * 8];
            uint32_t bfa[4][4], bfb[4][4];
            ldB4(wb, bfa);
            ldB4(wb +  16 * W_LD, bfb);  mma8(acc, hfr[0], bfa);
            ldB4(wb +  32 * W_LD, bfa);  mma8(acc, hfr[1], bfb);
            ldB4(wb +  48 * W_LD, bfb);  mma8(acc, hfr[2], bfa);
            ldB4(wb +  64 * W_LD, bfa);  mma8(acc, hfr[3], bfb);
            ldB4(wb +  80 * W_LD, bfb);  mma8(acc, hfr[4], bfa);
            ldB4(wb +  96 * W_LD, bfa);  mma8(acc, hfr[5], bfb);
            ldB4(wb + 112 * W_LD, bfb);  mma8(acc, hfr[6], bfa);
                                         mma8(acc, hfr[7], bfb);
            uint32_t af[4][4];
            #pragma unroll
            for (int kf = 0; kf < 4; kf++) {
                af[kf][0] = gelu2(pack_bf2(acc[2 * kf][0], acc[2 * kf][1]));
                af[kf][1] = gelu2(pack_bf2(acc[2 * kf][2], acc[2 * kf][3]));
                af[kf][2] = gelu2(pack_bf2(acc[2 * kf + 1][0], acc[2 * kf + 1][1]));
                af[kf][3] = gelu2(pack_bf2(acc[2 * kf + 1][2], acc[2 * kf + 1][3]));
            }
            #pragma unroll
            for (int kf = 0; kf < 4; kf++) {
                int k0 = cc * 64 + kf * 16;
                uint32_t addr =
                    smem_u32(&sW3[(k0 + (lane & 15)) * W3_LD + net * 8]);
                uint32_t b0, b1;
                ldsm_x2t(addr, b0, b1);
                mma_bf16(acc3, af[kf], b0, b1);
            }
        }

        // ---- stage s/t into sST[buf] ----
        if ((lane & 3) == 0) {
            int r1 = lane >> 2;
            #pragma unroll
            for (int half = 0; half < 2; half++) {
                int row = R0 + r1 + half * 8;
                sST[(net * 128 + row) * 2 + 0] = acc3[half * 2 + 0];
                sST[(net * 128 + row) * 2 + 1] = acc3[half * 2 + 1];
            }
        }

        // current-tile x into regs (pre-bar; sXA[buf] final since last iter)
        float4 xv = make_float4(0.f, 0.f, 0.f, 0.f);
        if (tid < 128)
            xv = *reinterpret_cast<float4*>(smem + OFF_XA + buf * 2048 + tid * 16);

        // finish next-tile prefetch: wait + x-keep conversion into xp[buf^1]
        if (has_next) {
            CP_WAIT0();
            if (tid < 128) {
                float4 nx = *reinterpret_cast<float4*>(
                    smem + OFF_XA + (buf ^ 1) * 2048 + tid * 16);
                float c4[4] = {nx.x, nx.y, nx.z, nx.w};
                *reinterpret_cast<__nv_bfloat162*>(
                    smem + OFF_XP + (buf ^ 1) * XP_BYTES + tid * 176 + 128) =
                    __floats2bfloat162_rn(c4[K0], c4[K1]);
            }
        }
        __syncthreads();

        // ---- epilogue: one thread per row ----
        if (tid < 128) {
            int row = tid;
            int b = base + row;
            float s0 = sST[row * 2 + 0] + sB3[0];
            float s1 = sST[row * 2 + 1] + sB3[1];
            float t0 = sST[(128 + row) * 2 + 0] + sB3[2];
            float t1 = sST[(128 + row) * 2 + 1] + sB3[3];
            float xc[4] = {xv.x, xv.y, xv.z, xv.w};
            float nx0 = xc[T0] * __expf(s0) + t0;
            float nx1 = xc[T1] * __expf(s1) + t1;
            float ld = s0 + s1;
            if (!FIRST) ld += g_ld[b];
            xc[T0] = nx0;
            xc[T1] = nx1;
            if (!LAST) {
                reinterpret_cast<float4*>(g_x)[b] =
                    make_float4(xc[0], xc[1], xc[2], xc[3]);
                g_ld[b] = ld;
            } else {
                float ss = xc[0] * xc[0] + xc[1] * xc[1] +
                           xc[2] * xc[2] + xc[3] * xc[3];
                out[b] = -0.5f * ss - 3.6757541328186907f + ld;
            }
        }
        buf ^= 1;
    }
}

extern "C" void kernel_launch(void* const* d_in, const int* in_sizes, int n_in,
                              void* d_out, int out_size)
{
    const float* theta = (const float*)d_in[0];
    const float* h     = (const float*)d_in[1];
    const float* sW1   = (const float*)d_in[2];
    const float* sb1   = (const float*)d_in[3];
    const float* sW2   = (const float*)d_in[4];
    const float* sb2   = (const float*)d_in[5];
    const float* sW3   = (const float*)d_in[6];
    const float* sb3   = (const float*)d_in[7];
    const float* tW1   = (const float*)d_in[8];
    const float* tb1   = (const float*)d_in[9];
    const float* tW2   = (const float*)d_in[10];
    const float* tb2   = (const float*)d_in[11];
    const float* tW3   = (const float*)d_in[12];
    const float* tb3   = (const float*)d_in[13];
    float* out = (float*)d_out;

    int nsm = 148;
    cudaDeviceGetAttribute(&nsm, cudaDevAttrMultiProcessorCount, 0);

    cudaFuncSetAttribute(nvp_layer<0>, cudaFuncAttributeMaxDynamicSharedMemorySize, SMEM_BYTES);
    cudaFuncSetAttribute(nvp_layer<1>, cudaFuncAttributeMaxDynamicSharedMemorySize, SMEM_BYTES);
    cudaFuncSetAttribute(nvp_layer<2>, cudaFuncAttributeMaxDynamicSharedMemorySize, SMEM_BYTES);
    cudaFuncSetAttribute(nvp_layer<3>, cudaFuncAttributeMaxDynamicSharedMemorySize, SMEM_BYTES);

    // pre-pass: h -> bf16 (BTOT*64 elems, 8 per thread, 256 threads/block)
    cvt_h_kernel<<<(BTOT * 64) / (8 * 256), 256>>>(h);

    dim3 grid(nsm), blk(NTHREADS);
    #define ARGS(L) theta, h,                                        \
        sW1 + (L) * 66 * 128, sb1 + (L) * 128,                       \
        sW2 + (L) * 128 * 128, sb2 + (L) * 128,                      \
        sW3 + (L) * 128 * 2, sb3 + (L) * 2,                          \
        tW1 + (L) * 66 * 128, tb1 + (L) * 128,                       \
        tW2 + (L) * 128 * 128, tb2 + (L) * 128,                      \
        tW3 + (L) * 128 * 2, tb3 + (L) * 2, out

    nvp_layer<0><<<grid, blk, SMEM_BYTES>>>(ARGS(0));
    nvp_layer<1><<<grid, blk, SMEM_BYTES>>>(ARGS(1));
    nvp_layer<2><<<grid, blk, SMEM_BYTES>>>(ARGS(2));
    nvp_layer<3><<<grid, blk, SMEM_BYTES>>>(ARGS(3));
    #undef ARGS
}